// round 13
// baseline (speedup 1.0000x reference)
#include <cuda_runtime.h>
#include <cuda_fp16.h>
#include <math.h>

// Problem constants (fixed by the reference)
#define NN 100000      // nodes
#define NE 1600000     // edges
#define FI 192         // input feats (64 latent + 128 X)
#define FH 128         // hidden feats
#define BN_EPS 1e-5f
#define NSCAN ((NN + 1023) / 1024)   // 98

// ---------------- device scratch (no allocs allowed) ----------------
// NOTE: graph is self-cleaning. g_deg is zeroed by k_out at the end of every
// call (static zero-init covers the first call); stats accumulators are zeroed
// at the top of k_degree (before any accumulation); g_cnt is zeroed in k_scan3.
__device__ __align__(128) __half g_h1h  [(size_t)NN * FH];  // 25.6 MB (fp16 gather payload)
__device__ __align__(128) __half g_agg1h[(size_t)NN * FH];  // 25.6 MB (fp16 post-agg payload)
__device__ __align__(16)  float  g_h2  [(size_t)NN * 2];
__device__ __align__(16)  float  g_agg2[(size_t)NN * 2];
__device__ float g_dinv[NN];
__device__ int   g_deg [NN];
__device__ int   g_rowptr[NN + 1];
__device__ int   g_cnt [NN];
__device__ __align__(16) int2 g_edge[NE];   // CSR by dst: {src, coef bits}
__device__ int   g_bsum[128];               // scan block sums
__device__ float g_sum1[FH], g_sq1[FH];
__device__ float g_sum2[2], g_sq2[2];

// ---------------- mma helpers ----------------
__device__ __forceinline__ void ldsm_x4(unsigned* r, const void* p) {
    unsigned a = (unsigned)__cvta_generic_to_shared(p);
    asm volatile("ldmatrix.sync.aligned.m8n8.x4.shared.b16 {%0,%1,%2,%3}, [%4];"
                 : "=r"(r[0]), "=r"(r[1]), "=r"(r[2]), "=r"(r[3]) : "r"(a));
}
__device__ __forceinline__ void ldsm_x4_t(unsigned* r, const void* p) {
    unsigned a = (unsigned)__cvta_generic_to_shared(p);
    asm volatile("ldmatrix.sync.aligned.m8n8.x4.trans.shared.b16 {%0,%1,%2,%3}, [%4];"
                 : "=r"(r[0]), "=r"(r[1]), "=r"(r[2]), "=r"(r[3]) : "r"(a));
}
__device__ __forceinline__ void mma16816(float* c, const unsigned* a, const unsigned* b) {
    asm volatile("mma.sync.aligned.m16n8k16.row.col.f32.f16.f16.f32 "
                 "{%0,%1,%2,%3}, {%4,%5,%6,%7}, {%8,%9}, {%0,%1,%2,%3};"
                 : "+f"(c[0]), "+f"(c[1]), "+f"(c[2]), "+f"(c[3])
                 : "r"(a[0]), "r"(a[1]), "r"(a[2]), "r"(a[3]), "r"(b[0]), "r"(b[1]));
}

// per-block edge-dtype detection: int64 little-endian => high words of the
// first 32 entries are all zero (values < 100000). 32 L2-hot loads + broadcast.
__device__ __forceinline__ int detect_is64(const int* __restrict__ ew, int* sflag) {
    if (threadIdx.x == 0) {
        int z = 0;
#pragma unroll
        for (int e = 0; e < 32; e++) z |= ew[2 * e + 1];
        *sflag = (z == 0) ? 1 : 0;
    }
    __syncthreads();
    return *sflag;
}

// ---------------- degree histogram by dst (+ zero stats accumulators) ----------------
__global__ void k_degree(const int* __restrict__ ew) {
    __shared__ int sflag;
    int is64 = detect_is64(ew, &sflag);
    int gtid = blockIdx.x * blockDim.x + threadIdx.x;
    // zero stats accumulators (runs strictly before anything accumulates)
    if (gtid < FH) { g_sum1[gtid] = 0.f; g_sq1[gtid] = 0.f; }
    if (gtid < 2)  { g_sum2[gtid] = 0.f; g_sq2[gtid] = 0.f; }
    int stride = gridDim.x * blockDim.x;
    for (int e = gtid; e < NE; e += stride) {
        int d = is64 ? ew[2 * ((size_t)NE + e)] : ew[(size_t)NE + e];
        atomicAdd(&g_deg[d], 1);
    }
}

// ---------------- scan phase 1 (+ fused dinv) ----------------
__global__ void k_scan1() {   // NSCAN blocks x 1024
    __shared__ int s[1024];
    int tid = threadIdx.x;
    int i = blockIdx.x * 1024 + tid;
    int v = 0;
    if (i < NN) {
        v = g_deg[i];
        g_dinv[i] = rsqrtf((float)(v + 1));
    }
    s[tid] = v;
    __syncthreads();
#pragma unroll
    for (int o = 1; o < 1024; o <<= 1) {
        int t = (tid >= o) ? s[tid - o] : 0;
        __syncthreads();
        s[tid] += t;
        __syncthreads();
    }
    if (i < NN) g_rowptr[i] = s[tid] - v;          // exclusive within block
    if (tid == 1023) g_bsum[blockIdx.x] = s[1023]; // block total
}

// ---------------- scan phase 2+3 fused: every block re-scans the 98 bsums ----------------
__global__ void k_scan3() {
    __shared__ int sb[128];
    int t = threadIdx.x;
    if (t < 128) sb[t] = (t < NSCAN) ? g_bsum[t] : 0;
    __syncthreads();
#pragma unroll
    for (int o = 1; o < 128; o <<= 1) {
        int v = 0;
        if (t < 128 && t >= o) v = sb[t - o];
        __syncthreads();
        if (t < 128) sb[t] += v;    // inclusive scan
        __syncthreads();
    }
    int i = blockIdx.x * blockDim.x + t;
    if (i < NN) {
        int b = i >> 10;
        int off = b ? sb[b - 1] : 0;
        g_rowptr[i] += off;
        g_cnt[i] = 0;
    }
    if (i == 0) g_rowptr[NN] = NE;
}

// ---------------- scatter edges into CSR (by dst), interleaved {src, coef} ----------------
__global__ void k_scatter(const int* __restrict__ ew) {
    __shared__ int sflag;
    int is64 = detect_is64(ew, &sflag);
    int stride = gridDim.x * blockDim.x;
    for (int e = blockIdx.x * blockDim.x + threadIdx.x; e < NE; e += stride) {
        int s, d;
        if (is64) { s = ew[2 * (size_t)e];  d = ew[2 * ((size_t)NE + e)]; }
        else      { s = ew[(size_t)e];      d = ew[(size_t)NE + e]; }
        int pos = g_rowptr[d] + atomicAdd(&g_cnt[d], 1);
        int2 rec;
        rec.x = s;
        rec.y = __float_as_int(g_dinv[s] * g_dinv[d]);
        g_edge[pos] = rec;
    }
}

// ---------------- GEMM1 (tensor cores): h1h = fp16([u_Y | X] @ W1) ----------------
#define SA_LD 40     // 32 + 8 halves padding
#define SB_LD 136    // 128 + 8 halves padding
__global__ __launch_bounds__(256, 2)
void k_gemm1(const float* __restrict__ X, const float* __restrict__ uY,
             const float* __restrict__ W1) {
    __shared__ __half sA[128][SA_LD];
    __shared__ __half sB[32][SB_LD];
    int tid   = threadIdx.x;
    int lane  = tid & 31;
    int wid   = tid >> 5;
    int warp_m = wid >> 1;          // 0..3
    int warp_n = wid & 1;           // 0..1
    int m0 = blockIdx.x * 128;

    float acc[2][8][4];
#pragma unroll
    for (int mi = 0; mi < 2; mi++)
#pragma unroll
        for (int ni = 0; ni < 8; ni++)
#pragma unroll
            for (int r = 0; r < 4; r++) acc[mi][ni][r] = 0.f;

    for (int kc = 0; kc < FI; kc += 32) {
#pragma unroll
        for (int r = 0; r < 4; r++) {
            int idx  = tid + r * 256;      // 0..1023
            int node = idx >> 3;           // 0..127
            int kq   = idx & 7;            // 0..7
            int gn   = m0 + node; if (gn >= NN) gn = NN - 1;
            int k    = kc + kq * 4;
            float4 v = (k < 64) ? *(const float4*)(uY + (size_t)gn * 64 + k)
                                : *(const float4*)(X  + (size_t)gn * 128 + (k - 64));
            *(__half2*)&sA[node][kq * 4]     = __floats2half2_rn(v.x, v.y);
            *(__half2*)&sA[node][kq * 4 + 2] = __floats2half2_rn(v.z, v.w);
        }
#pragma unroll
        for (int r = 0; r < 4; r++) {
            int idx = tid + r * 256;
            int k   = idx >> 5;            // 0..31
            int nq  = idx & 31;            // 0..31
            float4 v = *(const float4*)(W1 + (size_t)(kc + k) * FH + nq * 4);
            *(__half2*)&sB[k][nq * 4]     = __floats2half2_rn(v.x, v.y);
            *(__half2*)&sB[k][nq * 4 + 2] = __floats2half2_rn(v.z, v.w);
        }
        __syncthreads();

#pragma unroll
        for (int ck = 0; ck < 32; ck += 16) {
            unsigned a[2][4];
#pragma unroll
            for (int mi = 0; mi < 2; mi++) {
                int row = warp_m * 32 + mi * 16 + (lane & 15);
                int col = ck + (lane >> 4) * 8;
                ldsm_x4(a[mi], &sA[row][col]);
            }
            unsigned b[8][2];
#pragma unroll
            for (int bi = 0; bi < 4; bi++) {
                unsigned t4[4];
                int krow = ck + (lane & 15);
                int ncol = warp_n * 64 + bi * 16 + (lane >> 4) * 8;
                ldsm_x4_t(t4, &sB[krow][ncol]);
                b[2 * bi][0]     = t4[0]; b[2 * bi][1]     = t4[1];
                b[2 * bi + 1][0] = t4[2]; b[2 * bi + 1][1] = t4[3];
            }
#pragma unroll
            for (int mi = 0; mi < 2; mi++)
#pragma unroll
                for (int ni = 0; ni < 8; ni++)
                    mma16816(acc[mi][ni], a[mi], b[ni]);
        }
        __syncthreads();
    }

#pragma unroll
    for (int mi = 0; mi < 2; mi++) {
        int row = m0 + warp_m * 32 + mi * 16 + (lane >> 2);
#pragma unroll
        for (int ni = 0; ni < 8; ni++) {
            int col = warp_n * 64 + ni * 8 + (lane & 3) * 2;
            if (row < NN)
                *(__half2*)(g_h1h + (size_t)row * FH + col) =
                    __floats2half2_rn(acc[mi][ni][0], acc[mi][ni][1]);
            if (row + 8 < NN)
                *(__half2*)(g_h1h + (size_t)(row + 8) * FH + col) =
                    __floats2half2_rn(acc[mi][ni][2], acc[mi][ni][3]);
        }
    }
}

// ---------------- layer-1 aggregation: warp per dst row, 2 edges in flight ----------------
// Half-warp per edge: lane (f = lane&15) loads uint4 = 8 features (16B).
__global__ __launch_bounds__(256)
void k_agg1() {
    int gtid  = blockIdx.x * blockDim.x + threadIdx.x;
    int lane  = threadIdx.x & 31;
    int half  = lane >> 4;          // 0 or 1
    int fl    = lane & 15;          // feature-lane: features fl*8 .. fl*8+7
    int wid   = gtid >> 5;
    int nwarp = (gridDim.x * blockDim.x) >> 5;

    for (int row = wid; row < NN; row += nwarp) {
        int start = g_rowptr[row];
        int end   = g_rowptr[row + 1];

        float a0 = 0.f, a1 = 0.f, a2 = 0.f, a3 = 0.f;
        float a4 = 0.f, a5 = 0.f, a6 = 0.f, a7 = 0.f;
        if (half == 0) {   // self-loop term, lower half only
            float di = g_dinv[row];
            float dd = di * di;
            uint4 raw = *((const uint4*)(g_h1h + (size_t)row * FH) + fl);
            float2 f;
            f = __half22float2(*(const __half2*)&raw.x); a0 = f.x * dd; a1 = f.y * dd;
            f = __half22float2(*(const __half2*)&raw.y); a2 = f.x * dd; a3 = f.y * dd;
            f = __half22float2(*(const __half2*)&raw.z); a4 = f.x * dd; a5 = f.y * dd;
            f = __half22float2(*(const __half2*)&raw.w); a6 = f.x * dd; a7 = f.y * dd;
        }

        for (int i = start + half; i < end + half; i += 2) {
            int2 e = (i < end) ? g_edge[i] : make_int2(0, 0);   // dummy: coef 0.0f
            float c = __int_as_float(e.y);
            uint4 r = *((const uint4*)(g_h1h + (size_t)e.x * FH) + fl);
            float2 f;
            f = __half22float2(*(const __half2*)&r.x); a0 = fmaf(f.x, c, a0); a1 = fmaf(f.y, c, a1);
            f = __half22float2(*(const __half2*)&r.y); a2 = fmaf(f.x, c, a2); a3 = fmaf(f.y, c, a3);
            f = __half22float2(*(const __half2*)&r.z); a4 = fmaf(f.x, c, a4); a5 = fmaf(f.y, c, a5);
            f = __half22float2(*(const __half2*)&r.w); a6 = fmaf(f.x, c, a6); a7 = fmaf(f.y, c, a7);
        }

        a0 += __shfl_xor_sync(0xffffffffu, a0, 16);
        a1 += __shfl_xor_sync(0xffffffffu, a1, 16);
        a2 += __shfl_xor_sync(0xffffffffu, a2, 16);
        a3 += __shfl_xor_sync(0xffffffffu, a3, 16);
        a4 += __shfl_xor_sync(0xffffffffu, a4, 16);
        a5 += __shfl_xor_sync(0xffffffffu, a5, 16);
        a6 += __shfl_xor_sync(0xffffffffu, a6, 16);
        a7 += __shfl_xor_sync(0xffffffffu, a7, 16);

        if (half == 0) {
            uint4 o;
            *(__half2*)&o.x = __floats2half2_rn(a0, a1);
            *(__half2*)&o.y = __floats2half2_rn(a2, a3);
            *(__half2*)&o.z = __floats2half2_rn(a4, a5);
            *(__half2*)&o.w = __floats2half2_rn(a6, a7);
            *((uint4*)(g_agg1h + (size_t)row * FH) + fl) = o;
        }
    }
}

// ---------------- BN1 statistics (separate pass; proven-cheap atomic pattern) ----------------
#define BN1_NPB 128
__global__ void k_bn1_stats() {
    int j  = threadIdx.x;            // 0..127 feature
    int n0 = blockIdx.x * BN1_NPB;
    int n1 = n0 + BN1_NPB; if (n1 > NN) n1 = NN;
    float s = 0.f, q = 0.f;
    for (int n = n0; n < n1; n++) {
        float v = __half2float(g_agg1h[(size_t)n * FH + j]);
        s += v;
        q = fmaf(v, v, q);
    }
    atomicAdd(&g_sum1[j], s);
    atomicAdd(&g_sq1[j], q);
}

// ---------------- BN1 apply (params recomputed in-kernel) + ReLU + GEMM2 -> h2 ----------------
__global__ void k_layer2(const float* __restrict__ W2,
                         const float* __restrict__ gamma1, const float* __restrict__ beta1) {
    int gtid  = blockIdx.x * blockDim.x + threadIdx.x;
    int lane  = threadIdx.x & 31;
    int wid   = gtid >> 5;
    int nwarp = (gridDim.x * blockDim.x) >> 5;
    int f     = lane * 4;

    float4 sm = *(const float4*)&g_sum1[f];
    float4 sq = *(const float4*)&g_sq1[f];
    float4 gm = *(const float4*)&gamma1[f];
    float4 bt = *(const float4*)&beta1[f];
    float4 sc, sh;
    {
        float m, v;
        m = sm.x * (1.f / NN); v = sq.x * (1.f / NN) - m * m; sc.x = gm.x * rsqrtf(v + BN_EPS); sh.x = bt.x - m * sc.x;
        m = sm.y * (1.f / NN); v = sq.y * (1.f / NN) - m * m; sc.y = gm.y * rsqrtf(v + BN_EPS); sh.y = bt.y - m * sc.y;
        m = sm.z * (1.f / NN); v = sq.z * (1.f / NN) - m * m; sc.z = gm.z * rsqrtf(v + BN_EPS); sh.z = bt.z - m * sc.z;
        m = sm.w * (1.f / NN); v = sq.w * (1.f / NN) - m * m; sc.w = gm.w * rsqrtf(v + BN_EPS); sh.w = bt.w - m * sc.w;
    }
    const float4* w4 = (const float4*)W2;
    float4 wA = w4[lane * 2];
    float4 wB = w4[lane * 2 + 1];

    for (int node = wid; node < NN; node += nwarp) {
        uint2 raw = *((const uint2*)(g_agg1h + (size_t)node * FH) + lane);
        float2 f0 = __half22float2(*(const __half2*)&raw.x);
        float2 f1 = __half22float2(*(const __half2*)&raw.y);
        float y0 = fmaxf(fmaf(f0.x, sc.x, sh.x), 0.f);
        float y1 = fmaxf(fmaf(f0.y, sc.y, sh.y), 0.f);
        float y2 = fmaxf(fmaf(f1.x, sc.z, sh.z), 0.f);
        float y3 = fmaxf(fmaf(f1.y, sc.w, sh.w), 0.f);
        float p0 = y0 * wA.x + y1 * wA.z + y2 * wB.x + y3 * wB.z;
        float p1 = y0 * wA.y + y1 * wA.w + y2 * wB.y + y3 * wB.w;
#pragma unroll
        for (int o = 16; o; o >>= 1) {
            p0 += __shfl_xor_sync(0xffffffffu, p0, o);
            p1 += __shfl_xor_sync(0xffffffffu, p1, o);
        }
        if (lane == 0) {
            g_h2[(size_t)node * 2 + 0] = p0;
            g_h2[(size_t)node * 2 + 1] = p1;
        }
    }
}

// ---------------- layer-2 aggregation (unroll x4) + fused BN2 statistics ----------------
__global__ void k_agg2() {
    __shared__ float red[8][4];
    int lane   = threadIdx.x & 31;
    int warp   = threadIdx.x >> 5;
    int stride = gridDim.x * blockDim.x;

    float s0 = 0.f, q0 = 0.f, s1 = 0.f, q1 = 0.f;

    for (int row = blockIdx.x * blockDim.x + threadIdx.x; row < NN; row += stride) {
        int start = g_rowptr[row];
        int end   = g_rowptr[row + 1];
        float di  = g_dinv[row];
        float dd  = di * di;
        float2 h  = *(const float2*)(g_h2 + (size_t)row * 2);
        float a0 = h.x * dd, a1 = h.y * dd;
        int i = start;
        for (; i + 4 <= end; i += 4) {
            int2 e0 = g_edge[i],     e1 = g_edge[i + 1];
            int2 e2 = g_edge[i + 2], e3 = g_edge[i + 3];
            float2 h0 = *(const float2*)(g_h2 + (size_t)e0.x * 2);
            float2 h1 = *(const float2*)(g_h2 + (size_t)e1.x * 2);
            float2 h2 = *(const float2*)(g_h2 + (size_t)e2.x * 2);
            float2 h3 = *(const float2*)(g_h2 + (size_t)e3.x * 2);
            float c0 = __int_as_float(e0.y), c1 = __int_as_float(e1.y);
            float c2 = __int_as_float(e2.y), c3 = __int_as_float(e3.y);
            a0 = fmaf(h0.x, c0, fmaf(h1.x, c1, fmaf(h2.x, c2, fmaf(h3.x, c3, a0))));
            a1 = fmaf(h0.y, c0, fmaf(h1.y, c1, fmaf(h2.y, c2, fmaf(h3.y, c3, a1))));
        }
        for (; i < end; i++) {
            int2 e = g_edge[i];
            float c = __int_as_float(e.y);
            float2 hs = *(const float2*)(g_h2 + (size_t)e.x * 2);
            a0 = fmaf(hs.x, c, a0);
            a1 = fmaf(hs.y, c, a1);
        }
        g_agg2[(size_t)row * 2 + 0] = a0;
        g_agg2[(size_t)row * 2 + 1] = a1;
        s0 += a0; q0 = fmaf(a0, a0, q0);
        s1 += a1; q1 = fmaf(a1, a1, q1);
    }

#pragma unroll
    for (int o = 16; o; o >>= 1) {
        s0 += __shfl_xor_sync(0xffffffffu, s0, o);
        q0 += __shfl_xor_sync(0xffffffffu, q0, o);
        s1 += __shfl_xor_sync(0xffffffffu, s1, o);
        q1 += __shfl_xor_sync(0xffffffffu, q1, o);
    }
    if (lane == 0) { red[warp][0] = s0; red[warp][1] = q0; red[warp][2] = s1; red[warp][3] = q1; }
    __syncthreads();
    if (warp == 0 && lane < 4) {
        float acc = 0.f;
#pragma unroll
        for (int w = 0; w < 8; w++) acc += red[w][lane];
        float* dst[4] = { &g_sum2[0], &g_sq2[0], &g_sum2[1], &g_sq2[1] };
        atomicAdd(dst[lane], acc);
    }
}

// ---------------- BN2 + softmax (+ self-clean g_deg for next replay) ----------------
__global__ void k_out(const float* __restrict__ gamma2, const float* __restrict__ beta2,
                      float* __restrict__ out) {
    int i = blockIdx.x * blockDim.x + threadIdx.x;
    if (i >= NN) return;
    float m0 = g_sum2[0] * (1.f / NN);
    float v0 = g_sq2[0] * (1.f / NN) - m0 * m0;
    float m1 = g_sum2[1] * (1.f / NN);
    float v1 = g_sq2[1] * (1.f / NN) - m1 * m1;
    float sc0 = gamma2[0] * rsqrtf(v0 + BN_EPS);
    float sc1 = gamma2[1] * rsqrtf(v1 + BN_EPS);
    float sh0 = beta2[0] - m0 * sc0;
    float sh1 = beta2[1] - m1 * sc1;

    float2 a = *(const float2*)(g_agg2 + (size_t)i * 2);
    float y0 = fmaf(a.x, sc0, sh0);
    float y1 = fmaf(a.y, sc1, sh1);
    float mm = fmaxf(y0, y1);
    float e0 = expf(y0 - mm);
    float e1 = expf(y1 - mm);
    float inv = 1.f / (e0 + e1);
    ((float2*)out)[i] = make_float2(e0 * inv, e1 * inv);

    g_deg[i] = 0;   // self-clean for the next graph replay (nothing reads g_deg here)
}

// ---------------- launch ----------------
extern "C" void kernel_launch(void* const* d_in, const int* in_sizes, int n_in,
                              void* d_out, int out_size) {
    const int*   ew     = (const int*)  d_in[0];   // edge_index (int32 or int64, detected)
    const float* X      = (const float*)d_in[1];
    const float* uY     = (const float*)d_in[2];
    const float* W1     = (const float*)d_in[3];
    // d_in[4] = b1 (cancels under BatchNorm)
    const float* W2     = (const float*)d_in[5];
    // d_in[6] = b2 (cancels under BatchNorm)
    const float* gamma1 = (const float*)d_in[7];
    const float* beta1  = (const float*)d_in[8];
    const float* gamma2 = (const float*)d_in[9];
    const float* beta2  = (const float*)d_in[10];
    float* out = (float*)d_out;

    // Fork GEMM1 (depends only on X/uY/W1) onto a side stream. Handles are
    // deliberately not destroyed (destroying a capture-participating stream
    // invalidates the capture; replays execute no host code).
    cudaStream_t s2;
    cudaStreamCreateWithFlags(&s2, cudaStreamNonBlocking);
    cudaEvent_t eFork, eJoin;
    cudaEventCreateWithFlags(&eFork, cudaEventDisableTiming);
    cudaEventCreateWithFlags(&eJoin, cudaEventDisableTiming);

    cudaEventRecord(eFork, 0);
    cudaStreamWaitEvent(s2, eFork, 0);
    k_gemm1<<<(NN + 127) / 128, 256, 0, s2>>>(X, uY, W1);
    cudaEventRecord(eJoin, s2);

    // CSR preprocessing on the default stream, concurrent with gemm1
    k_degree  <<<1024, 256>>>(ew);
    k_scan1   <<<NSCAN, 1024>>>();
    k_scan3   <<<(NN + 255) / 256, 256>>>();
    k_scatter <<<1024, 256>>>(ew);

    cudaStreamWaitEvent(0, eJoin, 0);     // join: agg1 needs both h1h and CSR

    k_agg1    <<<2048, 256>>>();
    k_bn1_stats <<<(NN + BN1_NPB - 1) / BN1_NPB, 128>>>();
    k_layer2  <<<2048, 256>>>(W2, gamma1, beta1);
    k_agg2    <<<512, 256>>>();
    k_out     <<<(NN + 255) / 256, 256>>>(gamma2, beta2, out);
}

// round 14
// speedup vs baseline: 1.0690x; 1.0690x over previous
#include <cuda_runtime.h>
#include <cuda_fp16.h>
#include <math.h>

// Problem constants (fixed by the reference)
#define NN 100000      // nodes
#define NE 1600000     // edges
#define FI 192         // input feats (64 latent + 128 X)
#define FH 128         // hidden feats
#define BN_EPS 1e-5f
#define NSCAN ((NN + 1023) / 1024)   // 98

// ---------------- device scratch (no allocs allowed) ----------------
// NOTE: graph is self-cleaning. g_deg is zeroed by k_out at the end of every
// call (static zero-init covers the first call); stats accumulators are zeroed
// at the top of k_degree (before any accumulation); g_cnt is zeroed in k_scan3.
__device__ __align__(128) __half g_h1h  [(size_t)NN * FH];  // 25.6 MB (fp16 gather payload)
__device__ __align__(128) __half g_agg1h[(size_t)NN * FH];  // 25.6 MB (fp16 post-agg payload)
__device__ __align__(16)  float  g_h2  [(size_t)NN * 2];
__device__ __align__(16)  float  g_agg2[(size_t)NN * 2];
__device__ float g_dinv[NN];
__device__ int   g_deg [NN];
__device__ int   g_rowptr[NN + 1];
__device__ int   g_cnt [NN];
__device__ __align__(16) int2 g_edge[NE];   // CSR by dst: {src, coef bits}
__device__ int   g_bsum[128];               // scan block sums
__device__ float g_sum1[FH], g_sq1[FH];
__device__ float g_sum2[2], g_sq2[2];

// ---------------- mma helpers ----------------
__device__ __forceinline__ void ldsm_x4(unsigned* r, const void* p) {
    unsigned a = (unsigned)__cvta_generic_to_shared(p);
    asm volatile("ldmatrix.sync.aligned.m8n8.x4.shared.b16 {%0,%1,%2,%3}, [%4];"
                 : "=r"(r[0]), "=r"(r[1]), "=r"(r[2]), "=r"(r[3]) : "r"(a));
}
__device__ __forceinline__ void ldsm_x4_t(unsigned* r, const void* p) {
    unsigned a = (unsigned)__cvta_generic_to_shared(p);
    asm volatile("ldmatrix.sync.aligned.m8n8.x4.trans.shared.b16 {%0,%1,%2,%3}, [%4];"
                 : "=r"(r[0]), "=r"(r[1]), "=r"(r[2]), "=r"(r[3]) : "r"(a));
}
__device__ __forceinline__ void mma16816(float* c, const unsigned* a, const unsigned* b) {
    asm volatile("mma.sync.aligned.m16n8k16.row.col.f32.f16.f16.f32 "
                 "{%0,%1,%2,%3}, {%4,%5,%6,%7}, {%8,%9}, {%0,%1,%2,%3};"
                 : "+f"(c[0]), "+f"(c[1]), "+f"(c[2]), "+f"(c[3])
                 : "r"(a[0]), "r"(a[1]), "r"(a[2]), "r"(a[3]), "r"(b[0]), "r"(b[1]));
}

// per-block edge-dtype detection: int64 little-endian => high words of the
// first 32 entries are all zero (values < 100000). 32 L2-hot loads + broadcast.
__device__ __forceinline__ int detect_is64(const int* __restrict__ ew, int* sflag) {
    if (threadIdx.x == 0) {
        int z = 0;
#pragma unroll
        for (int e = 0; e < 32; e++) z |= ew[2 * e + 1];
        *sflag = (z == 0) ? 1 : 0;
    }
    __syncthreads();
    return *sflag;
}

// ---------------- degree histogram by dst (+ zero stats accumulators) ----------------
__global__ void k_degree(const int* __restrict__ ew) {
    __shared__ int sflag;
    int is64 = detect_is64(ew, &sflag);
    int gtid = blockIdx.x * blockDim.x + threadIdx.x;
    if (gtid < FH) { g_sum1[gtid] = 0.f; g_sq1[gtid] = 0.f; }
    if (gtid < 2)  { g_sum2[gtid] = 0.f; g_sq2[gtid] = 0.f; }
    int stride = gridDim.x * blockDim.x;
    for (int e = gtid; e < NE; e += stride) {
        int d = is64 ? ew[2 * ((size_t)NE + e)] : ew[(size_t)NE + e];
        atomicAdd(&g_deg[d], 1);
    }
}

// ---------------- scan phase 1 (+ fused dinv) ----------------
__global__ void k_scan1() {   // NSCAN blocks x 1024
    __shared__ int s[1024];
    int tid = threadIdx.x;
    int i = blockIdx.x * 1024 + tid;
    int v = 0;
    if (i < NN) {
        v = g_deg[i];
        g_dinv[i] = rsqrtf((float)(v + 1));
    }
    s[tid] = v;
    __syncthreads();
#pragma unroll
    for (int o = 1; o < 1024; o <<= 1) {
        int t = (tid >= o) ? s[tid - o] : 0;
        __syncthreads();
        s[tid] += t;
        __syncthreads();
    }
    if (i < NN) g_rowptr[i] = s[tid] - v;          // exclusive within block
    if (tid == 1023) g_bsum[blockIdx.x] = s[1023]; // block total
}

// ---------------- scan phase 2+3 fused: every block re-scans the 98 bsums ----------------
__global__ void k_scan3() {
    __shared__ int sb[128];
    int t = threadIdx.x;
    if (t < 128) sb[t] = (t < NSCAN) ? g_bsum[t] : 0;
    __syncthreads();
#pragma unroll
    for (int o = 1; o < 128; o <<= 1) {
        int v = 0;
        if (t < 128 && t >= o) v = sb[t - o];
        __syncthreads();
        if (t < 128) sb[t] += v;    // inclusive scan
        __syncthreads();
    }
    int i = blockIdx.x * blockDim.x + t;
    if (i < NN) {
        int b = i >> 10;
        int off = b ? sb[b - 1] : 0;
        g_rowptr[i] += off;
        g_cnt[i] = 0;
    }
    if (i == 0) g_rowptr[NN] = NE;
}

// ---------------- scatter edges into CSR (by dst), interleaved {src, coef} ----------------
__global__ void k_scatter(const int* __restrict__ ew) {
    __shared__ int sflag;
    int is64 = detect_is64(ew, &sflag);
    int stride = gridDim.x * blockDim.x;
    for (int e = blockIdx.x * blockDim.x + threadIdx.x; e < NE; e += stride) {
        int s, d;
        if (is64) { s = ew[2 * (size_t)e];  d = ew[2 * ((size_t)NE + e)]; }
        else      { s = ew[(size_t)e];      d = ew[(size_t)NE + e]; }
        int pos = g_rowptr[d] + atomicAdd(&g_cnt[d], 1);
        int2 rec;
        rec.x = s;
        rec.y = __float_as_int(g_dinv[s] * g_dinv[d]);
        g_edge[pos] = rec;
    }
}

// ---------------- GEMM1 (tensor cores, register-prefetch pipelined) ----------------
// h1h = fp16([u_Y | X] @ W1). Next K-chunk's global loads issued before the
// current chunk's MMAs so LDG latency overlaps tensor work.
#define SA_LD 40     // 32 + 8 halves padding
#define SB_LD 136    // 128 + 8 halves padding
__global__ __launch_bounds__(256, 2)
void k_gemm1(const float* __restrict__ X, const float* __restrict__ uY,
             const float* __restrict__ W1) {
    __shared__ __half sA[128][SA_LD];
    __shared__ __half sB[32][SB_LD];
    int tid   = threadIdx.x;
    int lane  = tid & 31;
    int wid   = tid >> 5;
    int warp_m = wid >> 1;          // 0..3
    int warp_n = wid & 1;           // 0..1
    int m0 = blockIdx.x * 128;

    // staging index precompute (4 float4 per thread for A and for B)
    int aNode[4], aK4[4], bK[4], bC4[4];
#pragma unroll
    for (int r = 0; r < 4; r++) {
        int idx = tid + r * 256;
        aNode[r] = idx >> 3;  aK4[r] = idx & 7;    // A: 128 nodes x 8 k-quads
        bK[r]    = idx >> 5;  bC4[r] = idx & 31;   // B: 32 k x 32 col-quads
    }
    int gnc[4];
#pragma unroll
    for (int r = 0; r < 4; r++) {
        int gn = m0 + aNode[r];
        gnc[r] = gn < NN ? gn : NN - 1;
    }

    float4 pa[4], pb[4];
    // prefetch chunk 0
#pragma unroll
    for (int r = 0; r < 4; r++) {
        int k = aK4[r] * 4;
        pa[r] = (k < 64) ? *(const float4*)(uY + (size_t)gnc[r] * 64 + k)
                         : *(const float4*)(X  + (size_t)gnc[r] * 128 + (k - 64));
        pb[r] = *(const float4*)(W1 + (size_t)bK[r] * FH + bC4[r] * 4);
    }

    float acc[2][8][4];
#pragma unroll
    for (int mi = 0; mi < 2; mi++)
#pragma unroll
        for (int ni = 0; ni < 8; ni++)
#pragma unroll
            for (int r = 0; r < 4; r++) acc[mi][ni][r] = 0.f;

    for (int kc = 0; kc < FI; kc += 32) {
        __syncthreads();   // previous tile's MMA reads complete
        // commit prefetched registers to smem (fp32 -> fp16)
#pragma unroll
        for (int r = 0; r < 4; r++) {
            *(__half2*)&sA[aNode[r]][aK4[r] * 4]     = __floats2half2_rn(pa[r].x, pa[r].y);
            *(__half2*)&sA[aNode[r]][aK4[r] * 4 + 2] = __floats2half2_rn(pa[r].z, pa[r].w);
            *(__half2*)&sB[bK[r]][bC4[r] * 4]        = __floats2half2_rn(pb[r].x, pb[r].y);
            *(__half2*)&sB[bK[r]][bC4[r] * 4 + 2]    = __floats2half2_rn(pb[r].z, pb[r].w);
        }
        __syncthreads();

        // prefetch next chunk while the MMAs below execute
        int kn = kc + 32;
        if (kn < FI) {
#pragma unroll
            for (int r = 0; r < 4; r++) {
                int k = kn + aK4[r] * 4;
                pa[r] = (k < 64) ? *(const float4*)(uY + (size_t)gnc[r] * 64 + k)
                                 : *(const float4*)(X  + (size_t)gnc[r] * 128 + (k - 64));
                pb[r] = *(const float4*)(W1 + (size_t)(kn + bK[r]) * FH + bC4[r] * 4);
            }
        }

#pragma unroll
        for (int ck = 0; ck < 32; ck += 16) {
            unsigned a[2][4];
#pragma unroll
            for (int mi = 0; mi < 2; mi++) {
                int row = warp_m * 32 + mi * 16 + (lane & 15);
                int col = ck + (lane >> 4) * 8;
                ldsm_x4(a[mi], &sA[row][col]);
            }
            unsigned b[8][2];
#pragma unroll
            for (int bi = 0; bi < 4; bi++) {
                unsigned t4[4];
                int krow = ck + (lane & 15);
                int ncol = warp_n * 64 + bi * 16 + (lane >> 4) * 8;
                ldsm_x4_t(t4, &sB[krow][ncol]);
                b[2 * bi][0]     = t4[0]; b[2 * bi][1]     = t4[1];
                b[2 * bi + 1][0] = t4[2]; b[2 * bi + 1][1] = t4[3];
            }
#pragma unroll
            for (int mi = 0; mi < 2; mi++)
#pragma unroll
                for (int ni = 0; ni < 8; ni++)
                    mma16816(acc[mi][ni], a[mi], b[ni]);
        }
    }

#pragma unroll
    for (int mi = 0; mi < 2; mi++) {
        int row = m0 + warp_m * 32 + mi * 16 + (lane >> 2);
#pragma unroll
        for (int ni = 0; ni < 8; ni++) {
            int col = warp_n * 64 + ni * 8 + (lane & 3) * 2;
            if (row < NN)
                *(__half2*)(g_h1h + (size_t)row * FH + col) =
                    __floats2half2_rn(acc[mi][ni][0], acc[mi][ni][1]);
            if (row + 8 < NN)
                *(__half2*)(g_h1h + (size_t)(row + 8) * FH + col) =
                    __floats2half2_rn(acc[mi][ni][2], acc[mi][ni][3]);
        }
    }
}

// ---------------- layer-1 aggregation: warp per dst row, 2 edges in flight ----------------
// Half-warp per edge: lane (f = lane&15) loads uint4 = 8 features (16B).
__global__ __launch_bounds__(256)
void k_agg1() {
    int gtid  = blockIdx.x * blockDim.x + threadIdx.x;
    int lane  = threadIdx.x & 31;
    int half  = lane >> 4;          // 0 or 1
    int fl    = lane & 15;          // feature-lane: features fl*8 .. fl*8+7
    int wid   = gtid >> 5;
    int nwarp = (gridDim.x * blockDim.x) >> 5;

    for (int row = wid; row < NN; row += nwarp) {
        int start = g_rowptr[row];
        int end   = g_rowptr[row + 1];

        float a0 = 0.f, a1 = 0.f, a2 = 0.f, a3 = 0.f;
        float a4 = 0.f, a5 = 0.f, a6 = 0.f, a7 = 0.f;
        if (half == 0) {   // self-loop term, lower half only
            float di = g_dinv[row];
            float dd = di * di;
            uint4 raw = *((const uint4*)(g_h1h + (size_t)row * FH) + fl);
            float2 f;
            f = __half22float2(*(const __half2*)&raw.x); a0 = f.x * dd; a1 = f.y * dd;
            f = __half22float2(*(const __half2*)&raw.y); a2 = f.x * dd; a3 = f.y * dd;
            f = __half22float2(*(const __half2*)&raw.z); a4 = f.x * dd; a5 = f.y * dd;
            f = __half22float2(*(const __half2*)&raw.w); a6 = f.x * dd; a7 = f.y * dd;
        }

        for (int i = start + half; i < end + half; i += 2) {
            int2 e = (i < end) ? g_edge[i] : make_int2(0, 0);   // dummy: coef 0.0f
            float c = __int_as_float(e.y);
            uint4 r = *((const uint4*)(g_h1h + (size_t)e.x * FH) + fl);
            float2 f;
            f = __half22float2(*(const __half2*)&r.x); a0 = fmaf(f.x, c, a0); a1 = fmaf(f.y, c, a1);
            f = __half22float2(*(const __half2*)&r.y); a2 = fmaf(f.x, c, a2); a3 = fmaf(f.y, c, a3);
            f = __half22float2(*(const __half2*)&r.z); a4 = fmaf(f.x, c, a4); a5 = fmaf(f.y, c, a5);
            f = __half22float2(*(const __half2*)&r.w); a6 = fmaf(f.x, c, a6); a7 = fmaf(f.y, c, a7);
        }

        a0 += __shfl_xor_sync(0xffffffffu, a0, 16);
        a1 += __shfl_xor_sync(0xffffffffu, a1, 16);
        a2 += __shfl_xor_sync(0xffffffffu, a2, 16);
        a3 += __shfl_xor_sync(0xffffffffu, a3, 16);
        a4 += __shfl_xor_sync(0xffffffffu, a4, 16);
        a5 += __shfl_xor_sync(0xffffffffu, a5, 16);
        a6 += __shfl_xor_sync(0xffffffffu, a6, 16);
        a7 += __shfl_xor_sync(0xffffffffu, a7, 16);

        if (half == 0) {
            uint4 o;
            *(__half2*)&o.x = __floats2half2_rn(a0, a1);
            *(__half2*)&o.y = __floats2half2_rn(a2, a3);
            *(__half2*)&o.z = __floats2half2_rn(a4, a5);
            *(__half2*)&o.w = __floats2half2_rn(a6, a7);
            *((uint4*)(g_agg1h + (size_t)row * FH) + fl) = o;
        }
    }
}

// ---------------- BN1 statistics (separate pass; proven-cheap atomic pattern) ----------------
#define BN1_NPB 128
__global__ void k_bn1_stats() {
    int j  = threadIdx.x;            // 0..127 feature
    int n0 = blockIdx.x * BN1_NPB;
    int n1 = n0 + BN1_NPB; if (n1 > NN) n1 = NN;
    float s = 0.f, q = 0.f;
    for (int n = n0; n < n1; n++) {
        float v = __half2float(g_agg1h[(size_t)n * FH + j]);
        s += v;
        q = fmaf(v, v, q);
    }
    atomicAdd(&g_sum1[j], s);
    atomicAdd(&g_sq1[j], q);
}

// ---------------- BN1 apply (params recomputed in-kernel) + ReLU + GEMM2 -> h2 ----------------
__global__ void k_layer2(const float* __restrict__ W2,
                         const float* __restrict__ gamma1, const float* __restrict__ beta1) {
    int gtid  = blockIdx.x * blockDim.x + threadIdx.x;
    int lane  = threadIdx.x & 31;
    int wid   = gtid >> 5;
    int nwarp = (gridDim.x * blockDim.x) >> 5;
    int f     = lane * 4;

    float4 sm = *(const float4*)&g_sum1[f];
    float4 sq = *(const float4*)&g_sq1[f];
    float4 gm = *(const float4*)&gamma1[f];
    float4 bt = *(const float4*)&beta1[f];
    float4 sc, sh;
    {
        float m, v;
        m = sm.x * (1.f / NN); v = sq.x * (1.f / NN) - m * m; sc.x = gm.x * rsqrtf(v + BN_EPS); sh.x = bt.x - m * sc.x;
        m = sm.y * (1.f / NN); v = sq.y * (1.f / NN) - m * m; sc.y = gm.y * rsqrtf(v + BN_EPS); sh.y = bt.y - m * sc.y;
        m = sm.z * (1.f / NN); v = sq.z * (1.f / NN) - m * m; sc.z = gm.z * rsqrtf(v + BN_EPS); sh.z = bt.z - m * sc.z;
        m = sm.w * (1.f / NN); v = sq.w * (1.f / NN) - m * m; sc.w = gm.w * rsqrtf(v + BN_EPS); sh.w = bt.w - m * sc.w;
    }
    const float4* w4 = (const float4*)W2;
    float4 wA = w4[lane * 2];
    float4 wB = w4[lane * 2 + 1];

    for (int node = wid; node < NN; node += nwarp) {
        uint2 raw = *((const uint2*)(g_agg1h + (size_t)node * FH) + lane);
        float2 f0 = __half22float2(*(const __half2*)&raw.x);
        float2 f1 = __half22float2(*(const __half2*)&raw.y);
        float y0 = fmaxf(fmaf(f0.x, sc.x, sh.x), 0.f);
        float y1 = fmaxf(fmaf(f0.y, sc.y, sh.y), 0.f);
        float y2 = fmaxf(fmaf(f1.x, sc.z, sh.z), 0.f);
        float y3 = fmaxf(fmaf(f1.y, sc.w, sh.w), 0.f);
        float p0 = y0 * wA.x + y1 * wA.z + y2 * wB.x + y3 * wB.z;
        float p1 = y0 * wA.y + y1 * wA.w + y2 * wB.y + y3 * wB.w;
#pragma unroll
        for (int o = 16; o; o >>= 1) {
            p0 += __shfl_xor_sync(0xffffffffu, p0, o);
            p1 += __shfl_xor_sync(0xffffffffu, p1, o);
        }
        if (lane == 0) {
            g_h2[(size_t)node * 2 + 0] = p0;
            g_h2[(size_t)node * 2 + 1] = p1;
        }
    }
}

// ---------------- layer-2 aggregation (unroll x4) + fused BN2 statistics ----------------
__global__ void k_agg2() {
    __shared__ float red[8][4];
    int lane   = threadIdx.x & 31;
    int warp   = threadIdx.x >> 5;
    int stride = gridDim.x * blockDim.x;

    float s0 = 0.f, q0 = 0.f, s1 = 0.f, q1 = 0.f;

    for (int row = blockIdx.x * blockDim.x + threadIdx.x; row < NN; row += stride) {
        int start = g_rowptr[row];
        int end   = g_rowptr[row + 1];
        float di  = g_dinv[row];
        float dd  = di * di;
        float2 h  = *(const float2*)(g_h2 + (size_t)row * 2);
        float a0 = h.x * dd, a1 = h.y * dd;
        int i = start;
        for (; i + 4 <= end; i += 4) {
            int2 e0 = g_edge[i],     e1 = g_edge[i + 1];
            int2 e2 = g_edge[i + 2], e3 = g_edge[i + 3];
            float2 h0 = *(const float2*)(g_h2 + (size_t)e0.x * 2);
            float2 h1 = *(const float2*)(g_h2 + (size_t)e1.x * 2);
            float2 h2 = *(const float2*)(g_h2 + (size_t)e2.x * 2);
            float2 h3 = *(const float2*)(g_h2 + (size_t)e3.x * 2);
            float c0 = __int_as_float(e0.y), c1 = __int_as_float(e1.y);
            float c2 = __int_as_float(e2.y), c3 = __int_as_float(e3.y);
            a0 = fmaf(h0.x, c0, fmaf(h1.x, c1, fmaf(h2.x, c2, fmaf(h3.x, c3, a0))));
            a1 = fmaf(h0.y, c0, fmaf(h1.y, c1, fmaf(h2.y, c2, fmaf(h3.y, c3, a1))));
        }
        for (; i < end; i++) {
            int2 e = g_edge[i];
            float c = __int_as_float(e.y);
            float2 hs = *(const float2*)(g_h2 + (size_t)e.x * 2);
            a0 = fmaf(hs.x, c, a0);
            a1 = fmaf(hs.y, c, a1);
        }
        g_agg2[(size_t)row * 2 + 0] = a0;
        g_agg2[(size_t)row * 2 + 1] = a1;
        s0 += a0; q0 = fmaf(a0, a0, q0);
        s1 += a1; q1 = fmaf(a1, a1, q1);
    }

#pragma unroll
    for (int o = 16; o; o >>= 1) {
        s0 += __shfl_xor_sync(0xffffffffu, s0, o);
        q0 += __shfl_xor_sync(0xffffffffu, q0, o);
        s1 += __shfl_xor_sync(0xffffffffu, s1, o);
        q1 += __shfl_xor_sync(0xffffffffu, q1, o);
    }
    if (lane == 0) { red[warp][0] = s0; red[warp][1] = q0; red[warp][2] = s1; red[warp][3] = q1; }
    __syncthreads();
    if (warp == 0 && lane < 4) {
        float acc = 0.f;
#pragma unroll
        for (int w = 0; w < 8; w++) acc += red[w][lane];
        float* dst[4] = { &g_sum2[0], &g_sq2[0], &g_sum2[1], &g_sq2[1] };
        atomicAdd(dst[lane], acc);
    }
}

// ---------------- BN2 + softmax (+ self-clean g_deg for next replay) ----------------
__global__ void k_out(const float* __restrict__ gamma2, const float* __restrict__ beta2,
                      float* __restrict__ out) {
    int i = blockIdx.x * blockDim.x + threadIdx.x;
    if (i >= NN) return;
    float m0 = g_sum2[0] * (1.f / NN);
    float v0 = g_sq2[0] * (1.f / NN) - m0 * m0;
    float m1 = g_sum2[1] * (1.f / NN);
    float v1 = g_sq2[1] * (1.f / NN) - m1 * m1;
    float sc0 = gamma2[0] * rsqrtf(v0 + BN_EPS);
    float sc1 = gamma2[1] * rsqrtf(v1 + BN_EPS);
    float sh0 = beta2[0] - m0 * sc0;
    float sh1 = beta2[1] - m1 * sc1;

    float2 a = *(const float2*)(g_agg2 + (size_t)i * 2);
    float y0 = fmaf(a.x, sc0, sh0);
    float y1 = fmaf(a.y, sc1, sh1);
    float mm = fmaxf(y0, y1);
    float e0 = expf(y0 - mm);
    float e1 = expf(y1 - mm);
    float inv = 1.f / (e0 + e1);
    ((float2*)out)[i] = make_float2(e0 * inv, e1 * inv);

    g_deg[i] = 0;   // self-clean for the next graph replay (nothing reads g_deg here)
}

// ---------------- launch ----------------
extern "C" void kernel_launch(void* const* d_in, const int* in_sizes, int n_in,
                              void* d_out, int out_size) {
    const int*   ew     = (const int*)  d_in[0];   // edge_index (int32 or int64, detected)
    const float* X      = (const float*)d_in[1];
    const float* uY     = (const float*)d_in[2];
    const float* W1     = (const float*)d_in[3];
    // d_in[4] = b1 (cancels under BatchNorm)
    const float* W2     = (const float*)d_in[5];
    // d_in[6] = b2 (cancels under BatchNorm)
    const float* gamma1 = (const float*)d_in[7];
    const float* beta1  = (const float*)d_in[8];
    const float* gamma2 = (const float*)d_in[9];
    const float* beta2  = (const float*)d_in[10];
    float* out = (float*)d_out;

    // Fork GEMM1 (depends only on X/uY/W1) onto a side stream. Handles are
    // deliberately not destroyed (destroying a capture-participating stream
    // invalidates the capture; replays execute no host code). GEMM1 is
    // enqueued AFTER the preprocessing chain host-side (events define the
    // true dependencies) so the ncu -s 5 slot lands on k_agg1.
    cudaStream_t s2;
    cudaStreamCreateWithFlags(&s2, cudaStreamNonBlocking);
    cudaEvent_t eFork, eJoin;
    cudaEventCreateWithFlags(&eFork, cudaEventDisableTiming);
    cudaEventCreateWithFlags(&eJoin, cudaEventDisableTiming);

    cudaEventRecord(eFork, 0);

    // CSR preprocessing on the default stream (concurrent with gemm1 below)
    k_degree  <<<1024, 256>>>(ew);
    k_scan1   <<<NSCAN, 1024>>>();
    k_scan3   <<<(NN + 255) / 256, 256>>>();
    k_scatter <<<1024, 256>>>(ew);

    cudaStreamWaitEvent(s2, eFork, 0);
    k_gemm1<<<(NN + 127) / 128, 256, 0, s2>>>(X, uY, W1);
    cudaEventRecord(eJoin, s2);

    cudaStreamWaitEvent(0, eJoin, 0);     // join: agg1 needs both h1h and CSR

    k_agg1    <<<2048, 256>>>();
    k_bn1_stats <<<(NN + BN1_NPB - 1) / BN1_NPB, 128>>>();
    k_layer2  <<<2048, 256>>>(W2, gamma1, beta1);
    k_agg2    <<<512, 256>>>();
    k_out     <<<(NN + 255) / 256, 256>>>(gamma2, beta2, out);
}

// round 15
// speedup vs baseline: 1.1252x; 1.0525x over previous
#include <cuda_runtime.h>
#include <cuda_fp16.h>
#include <math.h>

// Problem constants (fixed by the reference)
#define NN 100000      // nodes
#define NE 1600000     // edges
#define FI 192         // input feats (64 latent + 128 X)
#define FH 128         // hidden feats
#define BN_EPS 1e-5f
#define NSCAN ((NN + 1023) / 1024)   // 98

// ---------------- device scratch (no allocs allowed) ----------------
// NOTE: graph is self-cleaning. g_deg is zeroed by k_out at the end of every
// call (static zero-init covers the first call); stats accumulators are zeroed
// at the top of k_degree (before any accumulation); g_cnt is zeroed in k_scan3.
__device__ __align__(128) __half g_h1h  [(size_t)NN * FH];  // 25.6 MB (fp16 gather payload)
__device__ __align__(128) __half g_agg1h[(size_t)NN * FH];  // 25.6 MB (fp16 post-agg payload)
__device__ __align__(16)  float  g_h2  [(size_t)NN * 2];
__device__ __align__(16)  float  g_agg2[(size_t)NN * 2];
__device__ float g_dinv[NN];
__device__ int   g_deg [NN];
__device__ int   g_rowptr[NN + 1];
__device__ int   g_cnt [NN];
__device__ int   g_esrc[NE];     // CSR by dst: src node only (normalization is
                                 // algebraically factored: agg[d]=dinv[d]*(Σ dinv[s]h[s]+dinv[d]h[d]))
__device__ int   g_bsum[128];    // scan block sums
__device__ float g_sum1[FH], g_sq1[FH];
__device__ float g_sum2[2], g_sq2[2];

// ---------------- mma helpers ----------------
__device__ __forceinline__ void ldsm_x4(unsigned* r, const void* p) {
    unsigned a = (unsigned)__cvta_generic_to_shared(p);
    asm volatile("ldmatrix.sync.aligned.m8n8.x4.shared.b16 {%0,%1,%2,%3}, [%4];"
                 : "=r"(r[0]), "=r"(r[1]), "=r"(r[2]), "=r"(r[3]) : "r"(a));
}
__device__ __forceinline__ void ldsm_x4_t(unsigned* r, const void* p) {
    unsigned a = (unsigned)__cvta_generic_to_shared(p);
    asm volatile("ldmatrix.sync.aligned.m8n8.x4.trans.shared.b16 {%0,%1,%2,%3}, [%4];"
                 : "=r"(r[0]), "=r"(r[1]), "=r"(r[2]), "=r"(r[3]) : "r"(a));
}
__device__ __forceinline__ void mma16816(float* c, const unsigned* a, const unsigned* b) {
    asm volatile("mma.sync.aligned.m16n8k16.row.col.f32.f16.f16.f32 "
                 "{%0,%1,%2,%3}, {%4,%5,%6,%7}, {%8,%9}, {%0,%1,%2,%3};"
                 : "+f"(c[0]), "+f"(c[1]), "+f"(c[2]), "+f"(c[3])
                 : "r"(a[0]), "r"(a[1]), "r"(a[2]), "r"(a[3]), "r"(b[0]), "r"(b[1]));
}

// per-block edge-dtype detection: int64 little-endian => high words of the
// first 32 entries are all zero (values < 100000). 32 L2-hot loads + broadcast.
__device__ __forceinline__ int detect_is64(const int* __restrict__ ew, int* sflag) {
    if (threadIdx.x == 0) {
        int z = 0;
#pragma unroll
        for (int e = 0; e < 32; e++) z |= ew[2 * e + 1];
        *sflag = (z == 0) ? 1 : 0;
    }
    __syncthreads();
    return *sflag;
}

// ---------------- degree histogram by dst (+ zero stats accumulators) ----------------
__global__ void k_degree(const int* __restrict__ ew) {
    __shared__ int sflag;
    int is64 = detect_is64(ew, &sflag);
    int gtid = blockIdx.x * blockDim.x + threadIdx.x;
    if (gtid < FH) { g_sum1[gtid] = 0.f; g_sq1[gtid] = 0.f; }
    if (gtid < 2)  { g_sum2[gtid] = 0.f; g_sq2[gtid] = 0.f; }
    int stride = gridDim.x * blockDim.x;
    for (int e = gtid; e < NE; e += stride) {
        int d = is64 ? ew[2 * ((size_t)NE + e)] : ew[(size_t)NE + e];
        atomicAdd(&g_deg[d], 1);
    }
}

// ---------------- scan phase 1 (+ fused dinv) ----------------
__global__ void k_scan1() {   // NSCAN blocks x 1024
    __shared__ int s[1024];
    int tid = threadIdx.x;
    int i = blockIdx.x * 1024 + tid;
    int v = 0;
    if (i < NN) {
        v = g_deg[i];
        g_dinv[i] = rsqrtf((float)(v + 1));
    }
    s[tid] = v;
    __syncthreads();
#pragma unroll
    for (int o = 1; o < 1024; o <<= 1) {
        int t = (tid >= o) ? s[tid - o] : 0;
        __syncthreads();
        s[tid] += t;
        __syncthreads();
    }
    if (i < NN) g_rowptr[i] = s[tid] - v;          // exclusive within block
    if (tid == 1023) g_bsum[blockIdx.x] = s[1023]; // block total
}

// ---------------- scan phase 2+3 fused: every block re-scans the 98 bsums ----------------
__global__ void k_scan3() {
    __shared__ int sb[128];
    int t = threadIdx.x;
    if (t < 128) sb[t] = (t < NSCAN) ? g_bsum[t] : 0;
    __syncthreads();
#pragma unroll
    for (int o = 1; o < 128; o <<= 1) {
        int v = 0;
        if (t < 128 && t >= o) v = sb[t - o];
        __syncthreads();
        if (t < 128) sb[t] += v;    // inclusive scan
        __syncthreads();
    }
    int i = blockIdx.x * blockDim.x + t;
    if (i < NN) {
        int b = i >> 10;
        int off = b ? sb[b - 1] : 0;
        g_rowptr[i] += off;
        g_cnt[i] = 0;
    }
    if (i == 0) g_rowptr[NN] = NE;
}

// ---------------- scatter edges into CSR (by dst): src index ONLY ----------------
__global__ void k_scatter(const int* __restrict__ ew) {
    __shared__ int sflag;
    int is64 = detect_is64(ew, &sflag);
    int stride = gridDim.x * blockDim.x;
    for (int e = blockIdx.x * blockDim.x + threadIdx.x; e < NE; e += stride) {
        int s, d;
        if (is64) { s = ew[2 * (size_t)e];  d = ew[2 * ((size_t)NE + e)]; }
        else      { s = ew[(size_t)e];      d = ew[(size_t)NE + e]; }
        int pos = g_rowptr[d] + atomicAdd(&g_cnt[d], 1);
        g_esrc[pos] = s;
    }
}

// ---------------- GEMM1 (tensor cores, register-prefetch pipelined) ----------------
#define SA_LD 40     // 32 + 8 halves padding
#define SB_LD 136    // 128 + 8 halves padding
__global__ __launch_bounds__(256, 2)
void k_gemm1(const float* __restrict__ X, const float* __restrict__ uY,
             const float* __restrict__ W1) {
    __shared__ __half sA[128][SA_LD];
    __shared__ __half sB[32][SB_LD];
    int tid   = threadIdx.x;
    int lane  = tid & 31;
    int wid   = tid >> 5;
    int warp_m = wid >> 1;          // 0..3
    int warp_n = wid & 1;           // 0..1
    int m0 = blockIdx.x * 128;

    int aNode[4], aK4[4], bK[4], bC4[4];
#pragma unroll
    for (int r = 0; r < 4; r++) {
        int idx = tid + r * 256;
        aNode[r] = idx >> 3;  aK4[r] = idx & 7;
        bK[r]    = idx >> 5;  bC4[r] = idx & 31;
    }
    int gnc[4];
#pragma unroll
    for (int r = 0; r < 4; r++) {
        int gn = m0 + aNode[r];
        gnc[r] = gn < NN ? gn : NN - 1;
    }

    float4 pa[4], pb[4];
#pragma unroll
    for (int r = 0; r < 4; r++) {
        int k = aK4[r] * 4;
        pa[r] = (k < 64) ? *(const float4*)(uY + (size_t)gnc[r] * 64 + k)
                         : *(const float4*)(X  + (size_t)gnc[r] * 128 + (k - 64));
        pb[r] = *(const float4*)(W1 + (size_t)bK[r] * FH + bC4[r] * 4);
    }

    float acc[2][8][4];
#pragma unroll
    for (int mi = 0; mi < 2; mi++)
#pragma unroll
        for (int ni = 0; ni < 8; ni++)
#pragma unroll
            for (int r = 0; r < 4; r++) acc[mi][ni][r] = 0.f;

    for (int kc = 0; kc < FI; kc += 32) {
        __syncthreads();
#pragma unroll
        for (int r = 0; r < 4; r++) {
            *(__half2*)&sA[aNode[r]][aK4[r] * 4]     = __floats2half2_rn(pa[r].x, pa[r].y);
            *(__half2*)&sA[aNode[r]][aK4[r] * 4 + 2] = __floats2half2_rn(pa[r].z, pa[r].w);
            *(__half2*)&sB[bK[r]][bC4[r] * 4]        = __floats2half2_rn(pb[r].x, pb[r].y);
            *(__half2*)&sB[bK[r]][bC4[r] * 4 + 2]    = __floats2half2_rn(pb[r].z, pb[r].w);
        }
        __syncthreads();

        int kn = kc + 32;
        if (kn < FI) {
#pragma unroll
            for (int r = 0; r < 4; r++) {
                int k = kn + aK4[r] * 4;
                pa[r] = (k < 64) ? *(const float4*)(uY + (size_t)gnc[r] * 64 + k)
                                 : *(const float4*)(X  + (size_t)gnc[r] * 128 + (k - 64));
                pb[r] = *(const float4*)(W1 + (size_t)(kn + bK[r]) * FH + bC4[r] * 4);
            }
        }

#pragma unroll
        for (int ck = 0; ck < 32; ck += 16) {
            unsigned a[2][4];
#pragma unroll
            for (int mi = 0; mi < 2; mi++) {
                int row = warp_m * 32 + mi * 16 + (lane & 15);
                int col = ck + (lane >> 4) * 8;
                ldsm_x4(a[mi], &sA[row][col]);
            }
            unsigned b[8][2];
#pragma unroll
            for (int bi = 0; bi < 4; bi++) {
                unsigned t4[4];
                int krow = ck + (lane & 15);
                int ncol = warp_n * 64 + bi * 16 + (lane >> 4) * 8;
                ldsm_x4_t(t4, &sB[krow][ncol]);
                b[2 * bi][0]     = t4[0]; b[2 * bi][1]     = t4[1];
                b[2 * bi + 1][0] = t4[2]; b[2 * bi + 1][1] = t4[3];
            }
#pragma unroll
            for (int mi = 0; mi < 2; mi++)
#pragma unroll
                for (int ni = 0; ni < 8; ni++)
                    mma16816(acc[mi][ni], a[mi], b[ni]);
        }
    }

#pragma unroll
    for (int mi = 0; mi < 2; mi++) {
        int row = m0 + warp_m * 32 + mi * 16 + (lane >> 2);
#pragma unroll
        for (int ni = 0; ni < 8; ni++) {
            int col = warp_n * 64 + ni * 8 + (lane & 3) * 2;
            if (row < NN)
                *(__half2*)(g_h1h + (size_t)row * FH + col) =
                    __floats2half2_rn(acc[mi][ni][0], acc[mi][ni][1]);
            if (row + 8 < NN)
                *(__half2*)(g_h1h + (size_t)(row + 8) * FH + col) =
                    __floats2half2_rn(acc[mi][ni][2], acc[mi][ni][3]);
        }
    }
}

// ---------------- layer-1 aggregation: warp per dst row, 2 edges in flight ----------------
// agg[d] = dinv[d] * ( Σ_edges dinv[s]*h[s] + dinv[d]*h[d] ); per-edge weight
// is the L2-resident dinv[s] broadcast load (no materialized coef).
__global__ __launch_bounds__(256)
void k_agg1() {
    int gtid  = blockIdx.x * blockDim.x + threadIdx.x;
    int lane  = threadIdx.x & 31;
    int half  = lane >> 4;          // 0 or 1
    int fl    = lane & 15;          // feature-lane: features fl*8 .. fl*8+7
    int wid   = gtid >> 5;
    int nwarp = (gridDim.x * blockDim.x) >> 5;

    for (int row = wid; row < NN; row += nwarp) {
        int start = g_rowptr[row];
        int end   = g_rowptr[row + 1];
        float dinv_row = g_dinv[row];

        float a0 = 0.f, a1 = 0.f, a2 = 0.f, a3 = 0.f;
        float a4 = 0.f, a5 = 0.f, a6 = 0.f, a7 = 0.f;
        if (half == 0) {   // self-loop: contributes dinv[d]*h[d] to the inner sum
            float c = dinv_row;
            uint4 raw = *((const uint4*)(g_h1h + (size_t)row * FH) + fl);
            float2 f;
            f = __half22float2(*(const __half2*)&raw.x); a0 = f.x * c; a1 = f.y * c;
            f = __half22float2(*(const __half2*)&raw.y); a2 = f.x * c; a3 = f.y * c;
            f = __half22float2(*(const __half2*)&raw.z); a4 = f.x * c; a5 = f.y * c;
            f = __half22float2(*(const __half2*)&raw.w); a6 = f.x * c; a7 = f.y * c;
        }

        for (int i = start + half; i < end + half; i += 2) {
            int   s = (i < end) ? g_esrc[i] : row;
            float c = (i < end) ? g_dinv[s] : 0.f;   // dummy pad: zero weight
            uint4 r = *((const uint4*)(g_h1h + (size_t)s * FH) + fl);
            float2 f;
            f = __half22float2(*(const __half2*)&r.x); a0 = fmaf(f.x, c, a0); a1 = fmaf(f.y, c, a1);
            f = __half22float2(*(const __half2*)&r.y); a2 = fmaf(f.x, c, a2); a3 = fmaf(f.y, c, a3);
            f = __half22float2(*(const __half2*)&r.z); a4 = fmaf(f.x, c, a4); a5 = fmaf(f.y, c, a5);
            f = __half22float2(*(const __half2*)&r.w); a6 = fmaf(f.x, c, a6); a7 = fmaf(f.y, c, a7);
        }

        a0 += __shfl_xor_sync(0xffffffffu, a0, 16);
        a1 += __shfl_xor_sync(0xffffffffu, a1, 16);
        a2 += __shfl_xor_sync(0xffffffffu, a2, 16);
        a3 += __shfl_xor_sync(0xffffffffu, a3, 16);
        a4 += __shfl_xor_sync(0xffffffffu, a4, 16);
        a5 += __shfl_xor_sync(0xffffffffu, a5, 16);
        a6 += __shfl_xor_sync(0xffffffffu, a6, 16);
        a7 += __shfl_xor_sync(0xffffffffu, a7, 16);

        if (half == 0) {
            uint4 o;
            *(__half2*)&o.x = __floats2half2_rn(a0 * dinv_row, a1 * dinv_row);
            *(__half2*)&o.y = __floats2half2_rn(a2 * dinv_row, a3 * dinv_row);
            *(__half2*)&o.z = __floats2half2_rn(a4 * dinv_row, a5 * dinv_row);
            *(__half2*)&o.w = __floats2half2_rn(a6 * dinv_row, a7 * dinv_row);
            *((uint4*)(g_agg1h + (size_t)row * FH) + fl) = o;
        }
    }
}

// ---------------- BN1 statistics (separate pass; proven-cheap atomic pattern) ----------------
#define BN1_NPB 128
__global__ void k_bn1_stats() {
    int j  = threadIdx.x;            // 0..127 feature
    int n0 = blockIdx.x * BN1_NPB;
    int n1 = n0 + BN1_NPB; if (n1 > NN) n1 = NN;
    float s = 0.f, q = 0.f;
    for (int n = n0; n < n1; n++) {
        float v = __half2float(g_agg1h[(size_t)n * FH + j]);
        s += v;
        q = fmaf(v, v, q);
    }
    atomicAdd(&g_sum1[j], s);
    atomicAdd(&g_sq1[j], q);
}

// ---------------- BN1 apply (params recomputed in-kernel) + ReLU + GEMM2 -> h2 ----------------
__global__ void k_layer2(const float* __restrict__ W2,
                         const float* __restrict__ gamma1, const float* __restrict__ beta1) {
    int gtid  = blockIdx.x * blockDim.x + threadIdx.x;
    int lane  = threadIdx.x & 31;
    int wid   = gtid >> 5;
    int nwarp = (gridDim.x * blockDim.x) >> 5;
    int f     = lane * 4;

    float4 sm = *(const float4*)&g_sum1[f];
    float4 sq = *(const float4*)&g_sq1[f];
    float4 gm = *(const float4*)&gamma1[f];
    float4 bt = *(const float4*)&beta1[f];
    float4 sc, sh;
    {
        float m, v;
        m = sm.x * (1.f / NN); v = sq.x * (1.f / NN) - m * m; sc.x = gm.x * rsqrtf(v + BN_EPS); sh.x = bt.x - m * sc.x;
        m = sm.y * (1.f / NN); v = sq.y * (1.f / NN) - m * m; sc.y = gm.y * rsqrtf(v + BN_EPS); sh.y = bt.y - m * sc.y;
        m = sm.z * (1.f / NN); v = sq.z * (1.f / NN) - m * m; sc.z = gm.z * rsqrtf(v + BN_EPS); sh.z = bt.z - m * sc.z;
        m = sm.w * (1.f / NN); v = sq.w * (1.f / NN) - m * m; sc.w = gm.w * rsqrtf(v + BN_EPS); sh.w = bt.w - m * sc.w;
    }
    const float4* w4 = (const float4*)W2;
    float4 wA = w4[lane * 2];
    float4 wB = w4[lane * 2 + 1];

    for (int node = wid; node < NN; node += nwarp) {
        uint2 raw = *((const uint2*)(g_agg1h + (size_t)node * FH) + lane);
        float2 f0 = __half22float2(*(const __half2*)&raw.x);
        float2 f1 = __half22float2(*(const __half2*)&raw.y);
        float y0 = fmaxf(fmaf(f0.x, sc.x, sh.x), 0.f);
        float y1 = fmaxf(fmaf(f0.y, sc.y, sh.y), 0.f);
        float y2 = fmaxf(fmaf(f1.x, sc.z, sh.z), 0.f);
        float y3 = fmaxf(fmaf(f1.y, sc.w, sh.w), 0.f);
        float p0 = y0 * wA.x + y1 * wA.z + y2 * wB.x + y3 * wB.z;
        float p1 = y0 * wA.y + y1 * wA.w + y2 * wB.y + y3 * wB.w;
#pragma unroll
        for (int o = 16; o; o >>= 1) {
            p0 += __shfl_xor_sync(0xffffffffu, p0, o);
            p1 += __shfl_xor_sync(0xffffffffu, p1, o);
        }
        if (lane == 0) {
            g_h2[(size_t)node * 2 + 0] = p0;
            g_h2[(size_t)node * 2 + 1] = p1;
        }
    }
}

// ---------------- layer-2 aggregation (unroll x4) + fused BN2 statistics ----------------
__global__ void k_agg2() {
    __shared__ float red[8][4];
    int lane   = threadIdx.x & 31;
    int warp   = threadIdx.x >> 5;
    int stride = gridDim.x * blockDim.x;

    float s0 = 0.f, q0 = 0.f, s1 = 0.f, q1 = 0.f;

    for (int row = blockIdx.x * blockDim.x + threadIdx.x; row < NN; row += stride) {
        int start = g_rowptr[row];
        int end   = g_rowptr[row + 1];
        float dinv_row = g_dinv[row];
        float2 h  = *(const float2*)(g_h2 + (size_t)row * 2);
        float a0 = h.x * dinv_row, a1 = h.y * dinv_row;   // self-loop inner term
        int i = start;
        for (; i + 4 <= end; i += 4) {
            int e0 = g_esrc[i],     e1 = g_esrc[i + 1];
            int e2 = g_esrc[i + 2], e3 = g_esrc[i + 3];
            float2 h0 = *(const float2*)(g_h2 + (size_t)e0 * 2);
            float2 h1 = *(const float2*)(g_h2 + (size_t)e1 * 2);
            float2 h2 = *(const float2*)(g_h2 + (size_t)e2 * 2);
            float2 h3 = *(const float2*)(g_h2 + (size_t)e3 * 2);
            float c0 = g_dinv[e0], c1 = g_dinv[e1];
            float c2 = g_dinv[e2], c3 = g_dinv[e3];
            a0 = fmaf(h0.x, c0, fmaf(h1.x, c1, fmaf(h2.x, c2, fmaf(h3.x, c3, a0))));
            a1 = fmaf(h0.y, c0, fmaf(h1.y, c1, fmaf(h2.y, c2, fmaf(h3.y, c3, a1))));
        }
        for (; i < end; i++) {
            int e = g_esrc[i];
            float c = g_dinv[e];
            float2 hs = *(const float2*)(g_h2 + (size_t)e * 2);
            a0 = fmaf(hs.x, c, a0);
            a1 = fmaf(hs.y, c, a1);
        }
        a0 *= dinv_row;
        a1 *= dinv_row;
        g_agg2[(size_t)row * 2 + 0] = a0;
        g_agg2[(size_t)row * 2 + 1] = a1;
        s0 += a0; q0 = fmaf(a0, a0, q0);
        s1 += a1; q1 = fmaf(a1, a1, q1);
    }

#pragma unroll
    for (int o = 16; o; o >>= 1) {
        s0 += __shfl_xor_sync(0xffffffffu, s0, o);
        q0 += __shfl_xor_sync(0xffffffffu, q0, o);
        s1 += __shfl_xor_sync(0xffffffffu, s1, o);
        q1 += __shfl_xor_sync(0xffffffffu, q1, o);
    }
    if (lane == 0) { red[warp][0] = s0; red[warp][1] = q0; red[warp][2] = s1; red[warp][3] = q1; }
    __syncthreads();
    if (warp == 0 && lane < 4) {
        float acc = 0.f;
#pragma unroll
        for (int w = 0; w < 8; w++) acc += red[w][lane];
        float* dst[4] = { &g_sum2[0], &g_sq2[0], &g_sum2[1], &g_sq2[1] };
        atomicAdd(dst[lane], acc);
    }
}

// ---------------- BN2 + softmax (+ self-clean g_deg for next replay) ----------------
__global__ void k_out(const float* __restrict__ gamma2, const float* __restrict__ beta2,
                      float* __restrict__ out) {
    int i = blockIdx.x * blockDim.x + threadIdx.x;
    if (i >= NN) return;
    float m0 = g_sum2[0] * (1.f / NN);
    float v0 = g_sq2[0] * (1.f / NN) - m0 * m0;
    float m1 = g_sum2[1] * (1.f / NN);
    float v1 = g_sq2[1] * (1.f / NN) - m1 * m1;
    float sc0 = gamma2[0] * rsqrtf(v0 + BN_EPS);
    float sc1 = gamma2[1] * rsqrtf(v1 + BN_EPS);
    float sh0 = beta2[0] - m0 * sc0;
    float sh1 = beta2[1] - m1 * sc1;

    float2 a = *(const float2*)(g_agg2 + (size_t)i * 2);
    float y0 = fmaf(a.x, sc0, sh0);
    float y1 = fmaf(a.y, sc1, sh1);
    float mm = fmaxf(y0, y1);
    float e0 = expf(y0 - mm);
    float e1 = expf(y1 - mm);
    float inv = 1.f / (e0 + e1);
    ((float2*)out)[i] = make_float2(e0 * inv, e1 * inv);

    g_deg[i] = 0;   // self-clean for the next graph replay (nothing reads g_deg here)
}

// ---------------- launch ----------------
extern "C" void kernel_launch(void* const* d_in, const int* in_sizes, int n_in,
                              void* d_out, int out_size) {
    const int*   ew     = (const int*)  d_in[0];   // edge_index (int32 or int64, detected)
    const float* X      = (const float*)d_in[1];
    const float* uY     = (const float*)d_in[2];
    const float* W1     = (const float*)d_in[3];
    // d_in[4] = b1 (cancels under BatchNorm)
    const float* W2     = (const float*)d_in[5];
    // d_in[6] = b2 (cancels under BatchNorm)
    const float* gamma1 = (const float*)d_in[7];
    const float* beta1  = (const float*)d_in[8];
    const float* gamma2 = (const float*)d_in[9];
    const float* beta2  = (const float*)d_in[10];
    float* out = (float*)d_out;

    // Fork GEMM1 (depends only on X/uY/W1) onto a side stream. Handles are
    // deliberately not destroyed (destroying a capture-participating stream
    // invalidates the capture; replays execute no host code).
    cudaStream_t s2;
    cudaStreamCreateWithFlags(&s2, cudaStreamNonBlocking);
    cudaEvent_t eFork, eJoin;
    cudaEventCreateWithFlags(&eFork, cudaEventDisableTiming);
    cudaEventCreateWithFlags(&eJoin, cudaEventDisableTiming);

    cudaEventRecord(eFork, 0);

    // CSR preprocessing on the default stream (concurrent with gemm1 below)
    k_degree  <<<1024, 256>>>(ew);
    k_scan1   <<<NSCAN, 1024>>>();
    k_scan3   <<<(NN + 255) / 256, 256>>>();
    k_scatter <<<1024, 256>>>(ew);

    cudaStreamWaitEvent(s2, eFork, 0);
    k_gemm1<<<(NN + 127) / 128, 256, 0, s2>>>(X, uY, W1);
    cudaEventRecord(eJoin, s2);

    cudaStreamWaitEvent(0, eJoin, 0);     // join: agg1 needs both h1h and CSR

    k_agg1    <<<2048, 256>>>();
    k_bn1_stats <<<(NN + BN1_NPB - 1) / BN1_NPB, 128>>>();
    k_layer2  <<<2048, 256>>>(W2, gamma1, beta1);
    k_agg2    <<<512, 256>>>();
    k_out     <<<(NN + 255) / 256, 256>>>(gamma2, beta2, out);
}

// round 16
// speedup vs baseline: 1.1293x; 1.0037x over previous
#include <cuda_runtime.h>
#include <cuda_fp16.h>
#include <math.h>

// Problem constants (fixed by the reference)
#define NN 100000      // nodes
#define NE 1600000     // edges
#define FI 192         // input feats (64 latent + 128 X)
#define FH 128         // hidden feats
#define BN_EPS 1e-5f
#define NSCAN ((NN + 1023) / 1024)   // 98

// ---------------- device scratch (no allocs allowed) ----------------
// NOTE: graph is self-cleaning. g_deg is zeroed by k_out at the end of every
// call (static zero-init covers the first call); stats accumulators are zeroed
// at the top of k_degree (before any accumulation); g_rowcur is rebuilt by
// k_scan3 each call.
__device__ __align__(128) __half g_h1h  [(size_t)NN * FH];  // 25.6 MB (fp16 gather payload)
__device__ __align__(128) __half g_agg1h[(size_t)NN * FH];  // 25.6 MB (fp16 post-agg payload)
__device__ __align__(16)  float  g_h2  [(size_t)NN * 2];
__device__ __align__(16)  float  g_agg2[(size_t)NN * 2];
__device__ float g_dinv[NN];
__device__ int   g_deg [NN];
__device__ int   g_rowptr[NN + 1];
__device__ int   g_rowcur[NN];   // running CSR cursor (copy of rowptr; consumed by scatter's atomics)
__device__ int   g_esrc[NE];     // CSR by dst: src node only (normalization factored:
                                 // agg[d]=dinv[d]*(Σ dinv[s]h[s]+dinv[d]h[d]))
__device__ int   g_bsum[128];    // scan block sums
__device__ float g_sum1[FH], g_sq1[FH];
__device__ float g_sum2[2], g_sq2[2];

// ---------------- mma helpers ----------------
__device__ __forceinline__ void ldsm_x4(unsigned* r, const void* p) {
    unsigned a = (unsigned)__cvta_generic_to_shared(p);
    asm volatile("ldmatrix.sync.aligned.m8n8.x4.shared.b16 {%0,%1,%2,%3}, [%4];"
                 : "=r"(r[0]), "=r"(r[1]), "=r"(r[2]), "=r"(r[3]) : "r"(a));
}
__device__ __forceinline__ void ldsm_x4_t(unsigned* r, const void* p) {
    unsigned a = (unsigned)__cvta_generic_to_shared(p);
    asm volatile("ldmatrix.sync.aligned.m8n8.x4.trans.shared.b16 {%0,%1,%2,%3}, [%4];"
                 : "=r"(r[0]), "=r"(r[1]), "=r"(r[2]), "=r"(r[3]) : "r"(a));
}
__device__ __forceinline__ void mma16816(float* c, const unsigned* a, const unsigned* b) {
    asm volatile("mma.sync.aligned.m16n8k16.row.col.f32.f16.f16.f32 "
                 "{%0,%1,%2,%3}, {%4,%5,%6,%7}, {%8,%9}, {%0,%1,%2,%3};"
                 : "+f"(c[0]), "+f"(c[1]), "+f"(c[2]), "+f"(c[3])
                 : "r"(a[0]), "r"(a[1]), "r"(a[2]), "r"(a[3]), "r"(b[0]), "r"(b[1]));
}

// per-block edge-dtype detection: int64 little-endian => high words of the
// first 32 entries are all zero (values < 100000). 32 L2-hot loads + broadcast.
__device__ __forceinline__ int detect_is64(const int* __restrict__ ew, int* sflag) {
    if (threadIdx.x == 0) {
        int z = 0;
#pragma unroll
        for (int e = 0; e < 32; e++) z |= ew[2 * e + 1];
        *sflag = (z == 0) ? 1 : 0;
    }
    __syncthreads();
    return *sflag;
}

// ---------------- degree histogram by dst (+ zero stats accumulators) ----------------
__global__ void k_degree(const int* __restrict__ ew) {
    __shared__ int sflag;
    int is64 = detect_is64(ew, &sflag);
    int gtid = blockIdx.x * blockDim.x + threadIdx.x;
    if (gtid < FH) { g_sum1[gtid] = 0.f; g_sq1[gtid] = 0.f; }
    if (gtid < 2)  { g_sum2[gtid] = 0.f; g_sq2[gtid] = 0.f; }
    int stride = gridDim.x * blockDim.x;
    for (int e = gtid; e < NE; e += stride) {
        int d = is64 ? ew[2 * ((size_t)NE + e)] : ew[(size_t)NE + e];
        atomicAdd(&g_deg[d], 1);
    }
}

// ---------------- scan phase 1 (+ fused dinv) ----------------
__global__ void k_scan1() {   // NSCAN blocks x 1024
    __shared__ int s[1024];
    int tid = threadIdx.x;
    int i = blockIdx.x * 1024 + tid;
    int v = 0;
    if (i < NN) {
        v = g_deg[i];
        g_dinv[i] = rsqrtf((float)(v + 1));
    }
    s[tid] = v;
    __syncthreads();
#pragma unroll
    for (int o = 1; o < 1024; o <<= 1) {
        int t = (tid >= o) ? s[tid - o] : 0;
        __syncthreads();
        s[tid] += t;
        __syncthreads();
    }
    if (i < NN) g_rowptr[i] = s[tid] - v;          // exclusive within block
    if (tid == 1023) g_bsum[blockIdx.x] = s[1023]; // block total
}

// ---------------- scan phase 2+3 fused: finalize rowptr + seed rowcur ----------------
__global__ void k_scan3() {
    __shared__ int sb[128];
    int t = threadIdx.x;
    if (t < 128) sb[t] = (t < NSCAN) ? g_bsum[t] : 0;
    __syncthreads();
#pragma unroll
    for (int o = 1; o < 128; o <<= 1) {
        int v = 0;
        if (t < 128 && t >= o) v = sb[t - o];
        __syncthreads();
        if (t < 128) sb[t] += v;    // inclusive scan
        __syncthreads();
    }
    int i = blockIdx.x * blockDim.x + t;
    if (i < NN) {
        int b = i >> 10;
        int off = b ? sb[b - 1] : 0;
        int rp = g_rowptr[i] + off;
        g_rowptr[i] = rp;
        g_rowcur[i] = rp;   // scatter's running cursor (replaces rowptr-read + cnt-atomic)
    }
    if (i == 0) g_rowptr[NN] = NE;
}

// ---------------- scatter edges into CSR (by dst): single atomic per edge ----------------
__global__ void k_scatter(const int* __restrict__ ew) {
    __shared__ int sflag;
    int is64 = detect_is64(ew, &sflag);
    int stride = gridDim.x * blockDim.x;
    for (int e = blockIdx.x * blockDim.x + threadIdx.x; e < NE; e += stride) {
        int s, d;
        if (is64) { s = ew[2 * (size_t)e];  d = ew[2 * ((size_t)NE + e)]; }
        else      { s = ew[(size_t)e];      d = ew[(size_t)NE + e]; }
        int pos = atomicAdd(&g_rowcur[d], 1);
        g_esrc[pos] = s;
    }
}

// ---------------- GEMM1 (tensor cores, register-prefetch pipelined) ----------------
#define SA_LD 40     // 32 + 8 halves padding
#define SB_LD 136    // 128 + 8 halves padding
__global__ __launch_bounds__(256, 2)
void k_gemm1(const float* __restrict__ X, const float* __restrict__ uY,
             const float* __restrict__ W1) {
    __shared__ __half sA[128][SA_LD];
    __shared__ __half sB[32][SB_LD];
    int tid   = threadIdx.x;
    int lane  = tid & 31;
    int wid   = tid >> 5;
    int warp_m = wid >> 1;          // 0..3
    int warp_n = wid & 1;           // 0..1
    int m0 = blockIdx.x * 128;

    int aNode[4], aK4[4], bK[4], bC4[4];
#pragma unroll
    for (int r = 0; r < 4; r++) {
        int idx = tid + r * 256;
        aNode[r] = idx >> 3;  aK4[r] = idx & 7;
        bK[r]    = idx >> 5;  bC4[r] = idx & 31;
    }
    int gnc[4];
#pragma unroll
    for (int r = 0; r < 4; r++) {
        int gn = m0 + aNode[r];
        gnc[r] = gn < NN ? gn : NN - 1;
    }

    float4 pa[4], pb[4];
#pragma unroll
    for (int r = 0; r < 4; r++) {
        int k = aK4[r] * 4;
        pa[r] = (k < 64) ? *(const float4*)(uY + (size_t)gnc[r] * 64 + k)
                         : *(const float4*)(X  + (size_t)gnc[r] * 128 + (k - 64));
        pb[r] = *(const float4*)(W1 + (size_t)bK[r] * FH + bC4[r] * 4);
    }

    float acc[2][8][4];
#pragma unroll
    for (int mi = 0; mi < 2; mi++)
#pragma unroll
        for (int ni = 0; ni < 8; ni++)
#pragma unroll
            for (int r = 0; r < 4; r++) acc[mi][ni][r] = 0.f;

    for (int kc = 0; kc < FI; kc += 32) {
        __syncthreads();
#pragma unroll
        for (int r = 0; r < 4; r++) {
            *(__half2*)&sA[aNode[r]][aK4[r] * 4]     = __floats2half2_rn(pa[r].x, pa[r].y);
            *(__half2*)&sA[aNode[r]][aK4[r] * 4 + 2] = __floats2half2_rn(pa[r].z, pa[r].w);
            *(__half2*)&sB[bK[r]][bC4[r] * 4]        = __floats2half2_rn(pb[r].x, pb[r].y);
            *(__half2*)&sB[bK[r]][bC4[r] * 4 + 2]    = __floats2half2_rn(pb[r].z, pb[r].w);
        }
        __syncthreads();

        int kn = kc + 32;
        if (kn < FI) {
#pragma unroll
            for (int r = 0; r < 4; r++) {
                int k = kn + aK4[r] * 4;
                pa[r] = (k < 64) ? *(const float4*)(uY + (size_t)gnc[r] * 64 + k)
                                 : *(const float4*)(X  + (size_t)gnc[r] * 128 + (k - 64));
                pb[r] = *(const float4*)(W1 + (size_t)(kn + bK[r]) * FH + bC4[r] * 4);
            }
        }

#pragma unroll
        for (int ck = 0; ck < 32; ck += 16) {
            unsigned a[2][4];
#pragma unroll
            for (int mi = 0; mi < 2; mi++) {
                int row = warp_m * 32 + mi * 16 + (lane & 15);
                int col = ck + (lane >> 4) * 8;
                ldsm_x4(a[mi], &sA[row][col]);
            }
            unsigned b[8][2];
#pragma unroll
            for (int bi = 0; bi < 4; bi++) {
                unsigned t4[4];
                int krow = ck + (lane & 15);
                int ncol = warp_n * 64 + bi * 16 + (lane >> 4) * 8;
                ldsm_x4_t(t4, &sB[krow][ncol]);
                b[2 * bi][0]     = t4[0]; b[2 * bi][1]     = t4[1];
                b[2 * bi + 1][0] = t4[2]; b[2 * bi + 1][1] = t4[3];
            }
#pragma unroll
            for (int mi = 0; mi < 2; mi++)
#pragma unroll
                for (int ni = 0; ni < 8; ni++)
                    mma16816(acc[mi][ni], a[mi], b[ni]);
        }
    }

#pragma unroll
    for (int mi = 0; mi < 2; mi++) {
        int row = m0 + warp_m * 32 + mi * 16 + (lane >> 2);
#pragma unroll
        for (int ni = 0; ni < 8; ni++) {
            int col = warp_n * 64 + ni * 8 + (lane & 3) * 2;
            if (row < NN)
                *(__half2*)(g_h1h + (size_t)row * FH + col) =
                    __floats2half2_rn(acc[mi][ni][0], acc[mi][ni][1]);
            if (row + 8 < NN)
                *(__half2*)(g_h1h + (size_t)(row + 8) * FH + col) =
                    __floats2half2_rn(acc[mi][ni][2], acc[mi][ni][3]);
        }
    }
}

// ---------------- layer-1 aggregation: warp per dst row, 2 edges in flight ----------------
// agg[d] = dinv[d] * ( Σ_edges dinv[s]*h[s] + dinv[d]*h[d] )
__global__ __launch_bounds__(256)
void k_agg1() {
    int gtid  = blockIdx.x * blockDim.x + threadIdx.x;
    int lane  = threadIdx.x & 31;
    int half  = lane >> 4;          // 0 or 1
    int fl    = lane & 15;          // feature-lane: features fl*8 .. fl*8+7
    int wid   = gtid >> 5;
    int nwarp = (gridDim.x * blockDim.x) >> 5;

    for (int row = wid; row < NN; row += nwarp) {
        int start = g_rowptr[row];
        int end   = g_rowptr[row + 1];
        float dinv_row = g_dinv[row];

        float a0 = 0.f, a1 = 0.f, a2 = 0.f, a3 = 0.f;
        float a4 = 0.f, a5 = 0.f, a6 = 0.f, a7 = 0.f;
        if (half == 0) {   // self-loop: contributes dinv[d]*h[d] to the inner sum
            float c = dinv_row;
            uint4 raw = *((const uint4*)(g_h1h + (size_t)row * FH) + fl);
            float2 f;
            f = __half22float2(*(const __half2*)&raw.x); a0 = f.x * c; a1 = f.y * c;
            f = __half22float2(*(const __half2*)&raw.y); a2 = f.x * c; a3 = f.y * c;
            f = __half22float2(*(const __half2*)&raw.z); a4 = f.x * c; a5 = f.y * c;
            f = __half22float2(*(const __half2*)&raw.w); a6 = f.x * c; a7 = f.y * c;
        }

        for (int i = start + half; i < end + half; i += 2) {
            int   s = (i < end) ? g_esrc[i] : row;
            float c = (i < end) ? g_dinv[s] : 0.f;   // dummy pad: zero weight
            uint4 r = *((const uint4*)(g_h1h + (size_t)s * FH) + fl);
            float2 f;
            f = __half22float2(*(const __half2*)&r.x); a0 = fmaf(f.x, c, a0); a1 = fmaf(f.y, c, a1);
            f = __half22float2(*(const __half2*)&r.y); a2 = fmaf(f.x, c, a2); a3 = fmaf(f.y, c, a3);
            f = __half22float2(*(const __half2*)&r.z); a4 = fmaf(f.x, c, a4); a5 = fmaf(f.y, c, a5);
            f = __half22float2(*(const __half2*)&r.w); a6 = fmaf(f.x, c, a6); a7 = fmaf(f.y, c, a7);
        }

        a0 += __shfl_xor_sync(0xffffffffu, a0, 16);
        a1 += __shfl_xor_sync(0xffffffffu, a1, 16);
        a2 += __shfl_xor_sync(0xffffffffu, a2, 16);
        a3 += __shfl_xor_sync(0xffffffffu, a3, 16);
        a4 += __shfl_xor_sync(0xffffffffu, a4, 16);
        a5 += __shfl_xor_sync(0xffffffffu, a5, 16);
        a6 += __shfl_xor_sync(0xffffffffu, a6, 16);
        a7 += __shfl_xor_sync(0xffffffffu, a7, 16);

        if (half == 0) {
            uint4 o;
            *(__half2*)&o.x = __floats2half2_rn(a0 * dinv_row, a1 * dinv_row);
            *(__half2*)&o.y = __floats2half2_rn(a2 * dinv_row, a3 * dinv_row);
            *(__half2*)&o.z = __floats2half2_rn(a4 * dinv_row, a5 * dinv_row);
            *(__half2*)&o.w = __floats2half2_rn(a6 * dinv_row, a7 * dinv_row);
            *((uint4*)(g_agg1h + (size_t)row * FH) + fl) = o;
        }
    }
}

// ---------------- BN1 statistics (separate pass; proven-cheap atomic pattern) ----------------
#define BN1_NPB 128
__global__ void k_bn1_stats() {
    int j  = threadIdx.x;            // 0..127 feature
    int n0 = blockIdx.x * BN1_NPB;
    int n1 = n0 + BN1_NPB; if (n1 > NN) n1 = NN;
    float s = 0.f, q = 0.f;
    for (int n = n0; n < n1; n++) {
        float v = __half2float(g_agg1h[(size_t)n * FH + j]);
        s += v;
        q = fmaf(v, v, q);
    }
    atomicAdd(&g_sum1[j], s);
    atomicAdd(&g_sq1[j], q);
}

// ---------------- BN1 apply (params recomputed in-kernel) + ReLU + GEMM2 -> h2 ----------------
__global__ void k_layer2(const float* __restrict__ W2,
                         const float* __restrict__ gamma1, const float* __restrict__ beta1) {
    int gtid  = blockIdx.x * blockDim.x + threadIdx.x;
    int lane  = threadIdx.x & 31;
    int wid   = gtid >> 5;
    int nwarp = (gridDim.x * blockDim.x) >> 5;
    int f     = lane * 4;

    float4 sm = *(const float4*)&g_sum1[f];
    float4 sq = *(const float4*)&g_sq1[f];
    float4 gm = *(const float4*)&gamma1[f];
    float4 bt = *(const float4*)&beta1[f];
    float4 sc, sh;
    {
        float m, v;
        m = sm.x * (1.f / NN); v = sq.x * (1.f / NN) - m * m; sc.x = gm.x * rsqrtf(v + BN_EPS); sh.x = bt.x - m * sc.x;
        m = sm.y * (1.f / NN); v = sq.y * (1.f / NN) - m * m; sc.y = gm.y * rsqrtf(v + BN_EPS); sh.y = bt.y - m * sc.y;
        m = sm.z * (1.f / NN); v = sq.z * (1.f / NN) - m * m; sc.z = gm.z * rsqrtf(v + BN_EPS); sh.z = bt.z - m * sc.z;
        m = sm.w * (1.f / NN); v = sq.w * (1.f / NN) - m * m; sc.w = gm.w * rsqrtf(v + BN_EPS); sh.w = bt.w - m * sc.w;
    }
    const float4* w4 = (const float4*)W2;
    float4 wA = w4[lane * 2];
    float4 wB = w4[lane * 2 + 1];

    for (int node = wid; node < NN; node += nwarp) {
        uint2 raw = *((const uint2*)(g_agg1h + (size_t)node * FH) + lane);
        float2 f0 = __half22float2(*(const __half2*)&raw.x);
        float2 f1 = __half22float2(*(const __half2*)&raw.y);
        float y0 = fmaxf(fmaf(f0.x, sc.x, sh.x), 0.f);
        float y1 = fmaxf(fmaf(f0.y, sc.y, sh.y), 0.f);
        float y2 = fmaxf(fmaf(f1.x, sc.z, sh.z), 0.f);
        float y3 = fmaxf(fmaf(f1.y, sc.w, sh.w), 0.f);
        float p0 = y0 * wA.x + y1 * wA.z + y2 * wB.x + y3 * wB.z;
        float p1 = y0 * wA.y + y1 * wA.w + y2 * wB.y + y3 * wB.w;
#pragma unroll
        for (int o = 16; o; o >>= 1) {
            p0 += __shfl_xor_sync(0xffffffffu, p0, o);
            p1 += __shfl_xor_sync(0xffffffffu, p1, o);
        }
        if (lane == 0) {
            g_h2[(size_t)node * 2 + 0] = p0;
            g_h2[(size_t)node * 2 + 1] = p1;
        }
    }
}

// ---------------- layer-2 aggregation (unroll x4) + fused BN2 statistics ----------------
__global__ void k_agg2() {
    __shared__ float red[8][4];
    int lane   = threadIdx.x & 31;
    int warp   = threadIdx.x >> 5;
    int stride = gridDim.x * blockDim.x;

    float s0 = 0.f, q0 = 0.f, s1 = 0.f, q1 = 0.f;

    for (int row = blockIdx.x * blockDim.x + threadIdx.x; row < NN; row += stride) {
        int start = g_rowptr[row];
        int end   = g_rowptr[row + 1];
        float dinv_row = g_dinv[row];
        float2 h  = *(const float2*)(g_h2 + (size_t)row * 2);
        float a0 = h.x * dinv_row, a1 = h.y * dinv_row;   // self-loop inner term
        int i = start;
        for (; i + 4 <= end; i += 4) {
            int e0 = g_esrc[i],     e1 = g_esrc[i + 1];
            int e2 = g_esrc[i + 2], e3 = g_esrc[i + 3];
            float2 h0 = *(const float2*)(g_h2 + (size_t)e0 * 2);
            float2 h1 = *(const float2*)(g_h2 + (size_t)e1 * 2);
            float2 h2 = *(const float2*)(g_h2 + (size_t)e2 * 2);
            float2 h3 = *(const float2*)(g_h2 + (size_t)e3 * 2);
            float c0 = g_dinv[e0], c1 = g_dinv[e1];
            float c2 = g_dinv[e2], c3 = g_dinv[e3];
            a0 = fmaf(h0.x, c0, fmaf(h1.x, c1, fmaf(h2.x, c2, fmaf(h3.x, c3, a0))));
            a1 = fmaf(h0.y, c0, fmaf(h1.y, c1, fmaf(h2.y, c2, fmaf(h3.y, c3, a1))));
        }
        for (; i < end; i++) {
            int e = g_esrc[i];
            float c = g_dinv[e];
            float2 hs = *(const float2*)(g_h2 + (size_t)e * 2);
            a0 = fmaf(hs.x, c, a0);
            a1 = fmaf(hs.y, c, a1);
        }
        a0 *= dinv_row;
        a1 *= dinv_row;
        g_agg2[(size_t)row * 2 + 0] = a0;
        g_agg2[(size_t)row * 2 + 1] = a1;
        s0 += a0; q0 = fmaf(a0, a0, q0);
        s1 += a1; q1 = fmaf(a1, a1, q1);
    }

#pragma unroll
    for (int o = 16; o; o >>= 1) {
        s0 += __shfl_xor_sync(0xffffffffu, s0, o);
        q0 += __shfl_xor_sync(0xffffffffu, q0, o);
        s1 += __shfl_xor_sync(0xffffffffu, s1, o);
        q1 += __shfl_xor_sync(0xffffffffu, q1, o);
    }
    if (lane == 0) { red[warp][0] = s0; red[warp][1] = q0; red[warp][2] = s1; red[warp][3] = q1; }
    __syncthreads();
    if (warp == 0 && lane < 4) {
        float acc = 0.f;
#pragma unroll
        for (int w = 0; w < 8; w++) acc += red[w][lane];
        float* dst[4] = { &g_sum2[0], &g_sq2[0], &g_sum2[1], &g_sq2[1] };
        atomicAdd(dst[lane], acc);
    }
}

// ---------------- BN2 + softmax (+ self-clean g_deg for next replay) ----------------
__global__ void k_out(const float* __restrict__ gamma2, const float* __restrict__ beta2,
                      float* __restrict__ out) {
    int i = blockIdx.x * blockDim.x + threadIdx.x;
    if (i >= NN) return;
    float m0 = g_sum2[0] * (1.f / NN);
    float v0 = g_sq2[0] * (1.f / NN) - m0 * m0;
    float m1 = g_sum2[1] * (1.f / NN);
    float v1 = g_sq2[1] * (1.f / NN) - m1 * m1;
    float sc0 = gamma2[0] * rsqrtf(v0 + BN_EPS);
    float sc1 = gamma2[1] * rsqrtf(v1 + BN_EPS);
    float sh0 = beta2[0] - m0 * sc0;
    float sh1 = beta2[1] - m1 * sc1;

    float2 a = *(const float2*)(g_agg2 + (size_t)i * 2);
    float y0 = fmaf(a.x, sc0, sh0);
    float y1 = fmaf(a.y, sc1, sh1);
    float mm = fmaxf(y0, y1);
    float e0 = expf(y0 - mm);
    float e1 = expf(y1 - mm);
    float inv = 1.f / (e0 + e1);
    ((float2*)out)[i] = make_float2(e0 * inv, e1 * inv);

    g_deg[i] = 0;   // self-clean for the next graph replay (nothing reads g_deg here)
}

// ---------------- launch ----------------
extern "C" void kernel_launch(void* const* d_in, const int* in_sizes, int n_in,
                              void* d_out, int out_size) {
    const int*   ew     = (const int*)  d_in[0];   // edge_index (int32 or int64, detected)
    const float* X      = (const float*)d_in[1];
    const float* uY     = (const float*)d_in[2];
    const float* W1     = (const float*)d_in[3];
    // d_in[4] = b1 (cancels under BatchNorm)
    const float* W2     = (const float*)d_in[5];
    // d_in[6] = b2 (cancels under BatchNorm)
    const float* gamma1 = (const float*)d_in[7];
    const float* beta1  = (const float*)d_in[8];
    const float* gamma2 = (const float*)d_in[9];
    const float* beta2  = (const float*)d_in[10];
    float* out = (float*)d_out;

    // Fork GEMM1 (depends only on X/uY/W1) onto a side stream. Handles are
    // deliberately not destroyed (destroying a capture-participating stream
    // invalidates the capture; replays execute no host code).
    cudaStream_t s2;
    cudaStreamCreateWithFlags(&s2, cudaStreamNonBlocking);
    cudaEvent_t eFork, eJoin;
    cudaEventCreateWithFlags(&eFork, cudaEventDisableTiming);
    cudaEventCreateWithFlags(&eJoin, cudaEventDisableTiming);

    cudaEventRecord(eFork, 0);

    // CSR preprocessing on the default stream (concurrent with gemm1 below)
    k_degree  <<<1024, 256>>>(ew);
    k_scan1   <<<NSCAN, 1024>>>();
    k_scan3   <<<(NN + 255) / 256, 256>>>();
    k_scatter <<<1024, 256>>>(ew);

    cudaStreamWaitEvent(s2, eFork, 0);
    k_gemm1<<<(NN + 127) / 128, 256, 0, s2>>>(X, uY, W1);
    cudaEventRecord(eJoin, s2);

    cudaStreamWaitEvent(0, eJoin, 0);     // join: agg1 needs both h1h and CSR

    k_agg1    <<<2048, 256>>>();
    k_bn1_stats <<<(NN + BN1_NPB - 1) / BN1_NPB, 128>>>();
    k_layer2  <<<2048, 256>>>(W2, gamma1, beta1);
    k_agg2    <<<512, 256>>>();
    k_out     <<<(NN + 255) / 256, 256>>>(gamma2, beta2, out);
}